// round 6
// baseline (speedup 1.0000x reference)
#include <cuda_runtime.h>
#include <cuda_bf16.h>
#include <cstddef>

// Problem constants: B=4, T=2048, C=2048, H=16, G=4, HKV=4, D=128, KV=512
#define AT_B   4
#define AT_T   2048
#define AT_C   2048
#define AT_KV  512
#define AT_D   128
#define AT_H   16
#define AT_HKV 4
#define AT_SCALE 0.08838834764831845f  // 1/sqrt(128)

typedef unsigned long long u64;

// ---------------------------------------------------------------------------
// Packed fp32x2 helpers (sm_103a): 2 FMAs per instruction, doubles fp32 rate.
// ---------------------------------------------------------------------------
__device__ __forceinline__ u64 ffma2(u64 a, u64 b, u64 c) {
    u64 d;
    asm("fma.rn.f32x2 %0, %1, %2, %3;" : "=l"(d) : "l"(a), "l"(b), "l"(c));
    return d;
}
__device__ __forceinline__ u64 fmul2(u64 a, u64 b) {
    u64 d;
    asm("mul.rn.f32x2 %0, %1, %2;" : "=l"(d) : "l"(a), "l"(b));
    return d;
}
__device__ __forceinline__ u64 dup2(float x) {
    u64 r;
    asm("mov.b64 %0, {%1, %1};" : "=l"(r) : "f"(x));
    return r;
}
__device__ __forceinline__ float2 unpk(u64 v) {
    float2 r;
    asm("mov.b64 {%0, %1}, %2;" : "=f"(r.x), "=f"(r.y) : "l"(v));
    return r;
}

// ---------------------------------------------------------------------------
// Scratch (allocation-free rule: __device__ globals)
// ---------------------------------------------------------------------------
__device__ float g_xq[AT_B * AT_T * AT_C];   // 64 MB
__device__ float g_xk[AT_B * AT_T * AT_KV];  // 16 MB
__device__ float g_xv[AT_B * AT_T * AT_KV];  // 16 MB
__device__ float g_xo[AT_B * AT_T * AT_C];   // 64 MB

// ---------------------------------------------------------------------------
// SGEMM: out[M,N] = A[M,K] @ W[N,K]^T + bias[N]
// 128x128 block tile, BK=8, 256 threads, 8x8 microtile (4 quadrants of 4x4),
// double-buffered smem, f32x2 FMA. Requires M%128==0, N%128==0, K%8==0.
// ---------------------------------------------------------------------------
__global__ __launch_bounds__(256, 2)
void gemm_bias_kernel(const float* __restrict__ A, const float* __restrict__ W,
                      const float* __restrict__ bias, float* __restrict__ out,
                      int N, int K)
{
    __shared__ float As[2][8][132];  // [k][m], pad 132 -> conflict-free stores/loads
    __shared__ float Bs[2][8][132];  // [k][n]

    const int tid  = threadIdx.x;
    const int lrow = tid >> 1;          // 0..127
    const int lcol = (tid & 1) << 2;    // 0 or 4
    const float* Ab = A + (size_t)(blockIdx.y * 128 + lrow) * K + lcol;
    const float* Wb = W + (size_t)(blockIdx.x * 128 + lrow) * K + lcol;

    float4 a4 = *(const float4*)Ab;
    float4 w4 = *(const float4*)Wb;
    As[0][lcol+0][lrow]=a4.x; As[0][lcol+1][lrow]=a4.y;
    As[0][lcol+2][lrow]=a4.z; As[0][lcol+3][lrow]=a4.w;
    Bs[0][lcol+0][lrow]=w4.x; Bs[0][lcol+1][lrow]=w4.y;
    Bs[0][lcol+2][lrow]=w4.z; Bs[0][lcol+3][lrow]=w4.w;
    __syncthreads();

    const int tx = tid & 15, ty = tid >> 4;
    u64 acc[8][4];
    #pragma unroll
    for (int i = 0; i < 8; i++)
        #pragma unroll
        for (int j = 0; j < 4; j++) acc[i][j] = 0ull;

    const int nk = K >> 3;
    int buf = 0;
    for (int kt = 0; kt < nk; kt++) {
        if (kt + 1 < nk) {
            a4 = *(const float4*)(Ab + (size_t)(kt + 1) * 8);
            w4 = *(const float4*)(Wb + (size_t)(kt + 1) * 8);
        }
        #pragma unroll
        for (int k = 0; k < 8; k++) {
            float4 aA = *(const float4*)&As[buf][k][ty * 4];
            float4 aB = *(const float4*)&As[buf][k][64 + ty * 4];
            ulonglong2 b01 = *(const ulonglong2*)&Bs[buf][k][tx * 4];       // cols tx*4..+3
            ulonglong2 b23 = *(const ulonglong2*)&Bs[buf][k][64 + tx * 4];  // cols 64+tx*4..+3
            float av[8] = {aA.x, aA.y, aA.z, aA.w, aB.x, aB.y, aB.z, aB.w};
            #pragma unroll
            for (int i = 0; i < 8; i++) {
                u64 ad = dup2(av[i]);
                acc[i][0] = ffma2(ad, b01.x, acc[i][0]);
                acc[i][1] = ffma2(ad, b01.y, acc[i][1]);
                acc[i][2] = ffma2(ad, b23.x, acc[i][2]);
                acc[i][3] = ffma2(ad, b23.y, acc[i][3]);
            }
        }
        buf ^= 1;
        if (kt + 1 < nk) {
            As[buf][lcol+0][lrow]=a4.x; As[buf][lcol+1][lrow]=a4.y;
            As[buf][lcol+2][lrow]=a4.z; As[buf][lcol+3][lrow]=a4.w;
            Bs[buf][lcol+0][lrow]=w4.x; Bs[buf][lcol+1][lrow]=w4.y;
            Bs[buf][lcol+2][lrow]=w4.z; Bs[buf][lcol+3][lrow]=w4.w;
        }
        __syncthreads();
    }

    const int ocol0 = blockIdx.x * 128 + tx * 4;
    const int orow0 = blockIdx.y * 128 + ty * 4;
    float4 bA = *(const float4*)(bias + ocol0);
    float4 bB = *(const float4*)(bias + ocol0 + 64);
    #pragma unroll
    for (int i = 0; i < 8; i++) {
        int r = orow0 + ((i < 4) ? i : (60 + i));  // rows ty*4+0..3 and 64+ty*4+0..3
        float2 p0 = unpk(acc[i][0]);
        float2 p1 = unpk(acc[i][1]);
        float2 p2 = unpk(acc[i][2]);
        float2 p3 = unpk(acc[i][3]);
        float4 oA = make_float4(p0.x + bA.x, p0.y + bA.y, p1.x + bA.z, p1.y + bA.w);
        float4 oB = make_float4(p2.x + bB.x, p2.y + bB.y, p3.x + bB.z, p3.y + bB.w);
        *(float4*)(out + (size_t)r * N + ocol0)      = oA;
        *(float4*)(out + (size_t)r * N + ocol0 + 64) = oB;
    }
}

// ---------------------------------------------------------------------------
// Flash attention (causal, GQA). One block = 64 query rows of one (b,h).
// 256 threads = 16x16 grid; thread owns S[4r x 4c strided], O[4r x 4 d-pairs].
// f32x2 FMA in both QK^T (pair over d) and PV (pair over d). Softmax row
// reductions via half-warp shuffles (rows owned per ty-group).
// ---------------------------------------------------------------------------
__global__ __launch_bounds__(256, 1)
void attn_kernel()
{
    extern __shared__ float smem[];
    float* Qs = smem;                    // [64][130] (pad 130: 8B-aligned d-pairs, conflict-free)
    float* Ks = smem + 64 * 130;         // [64][130]
    float* Vs = smem + 2 * 64 * 130;     // [64][128]
    float* Ps = Vs + 64 * 128;           // [64][68]

    const int tid = threadIdx.x;
    const int tx = tid & 15, ty = tid >> 4;
    const int qb  = (AT_T / 64 - 1) - blockIdx.x;  // heavy blocks first
    const int bh  = blockIdx.y;
    const int b   = bh >> 4;
    const int h   = bh & 15;
    const int hkv = h & 3;

    const float* qp = g_xq + (size_t)b * AT_T * AT_C  + h   * AT_D;
    const float* kp = g_xk + (size_t)b * AT_T * AT_KV + hkv * AT_D;
    const float* vp = g_xv + (size_t)b * AT_T * AT_KV + hkv * AT_D;
    float*       op = g_xo + (size_t)b * AT_T * AT_C  + h   * AT_D;

    const int q0 = qb * 64;

    // Load Q tile (64 x 128) once
    for (int i = tid; i < 64 * 32; i += 256) {
        int row = i >> 5, c4 = (i & 31) << 2;
        float4 v = *(const float4*)(qp + (size_t)(q0 + row) * AT_C + c4);
        float* dst = Qs + row * 130 + c4;
        dst[0] = v.x; dst[1] = v.y; dst[2] = v.z; dst[3] = v.w;
    }

    float m[4], l[4];
    u64 o2[4][4];
    #pragma unroll
    for (int r = 0; r < 4; r++) {
        m[r] = -1e30f; l[r] = 0.f;
        #pragma unroll
        for (int p = 0; p < 4; p++) o2[r][p] = 0ull;
    }

    for (int j = 0; j <= qb; j++) {
        __syncthreads();  // previous tile fully consumed
        for (int i = tid; i < 64 * 32; i += 256) {
            int row = i >> 5, c4 = (i & 31) << 2;
            const size_t off = (size_t)(j * 64 + row) * AT_KV + c4;
            float4 kv = *(const float4*)(kp + off);
            float4 vv = *(const float4*)(vp + off);
            float* kd = Ks + row * 130 + c4;
            kd[0] = kv.x; kd[1] = kv.y; kd[2] = kv.z; kd[3] = kv.w;
            *(float4*)(Vs + row * 128 + c4) = vv;
        }
        __syncthreads();

        // S = Q K^T  (pairs over d; horizontal add at the end)
        u64 s2[4][4];
        #pragma unroll
        for (int r = 0; r < 4; r++)
            #pragma unroll
            for (int c = 0; c < 4; c++) s2[r][c] = 0ull;

        #pragma unroll 4
        for (int d = 0; d < 128; d += 2) {
            u64 q2[4], k2[4];
            #pragma unroll
            for (int r = 0; r < 4; r++)
                q2[r] = *(const u64*)(Qs + (ty * 4 + r) * 130 + d);
            #pragma unroll
            for (int c = 0; c < 4; c++)
                k2[c] = *(const u64*)(Ks + (tx + 16 * c) * 130 + d);
            #pragma unroll
            for (int r = 0; r < 4; r++)
                #pragma unroll
                for (int c = 0; c < 4; c++)
                    s2[r][c] = ffma2(q2[r], k2[c], s2[r][c]);
        }

        // Online softmax per row (rows owned by ty-group; reduce across 16 tx lanes)
        #pragma unroll
        for (int r = 0; r < 4; r++) {
            const int row = ty * 4 + r;
            const int qi  = q0 + row;
            float s[4];
            #pragma unroll
            for (int c = 0; c < 4; c++) {
                float2 p = unpk(s2[r][c]);
                s[c] = (p.x + p.y) * AT_SCALE;
                if (j * 64 + tx + 16 * c > qi) s[c] = -1e30f;  // causal mask
            }
            float mx = fmaxf(fmaxf(s[0], s[1]), fmaxf(s[2], s[3]));
            #pragma unroll
            for (int off = 8; off > 0; off >>= 1)
                mx = fmaxf(mx, __shfl_xor_sync(0xffffffffu, mx, off));
            float newm = fmaxf(m[r], mx);
            float corr = __expf(m[r] - newm);
            float rs = 0.f;
            #pragma unroll
            for (int c = 0; c < 4; c++) {
                float p = __expf(s[c] - newm);
                Ps[row * 68 + tx + 16 * c] = p;
                rs += p;
            }
            #pragma unroll
            for (int off = 8; off > 0; off >>= 1)
                rs += __shfl_xor_sync(0xffffffffu, rs, off);
            l[r] = l[r] * corr + rs;
            m[r] = newm;
            u64 c2 = dup2(corr);
            #pragma unroll
            for (int p = 0; p < 4; p++) o2[r][p] = fmul2(o2[r][p], c2);
        }
        __syncthreads();  // Ps ready for everyone

        // O += P V   (d-pairs contiguous: thread owns d = 2*(tx+16p)+{0,1})
        #pragma unroll 2
        for (int c = 0; c < 64; c++) {
            u64 v2[4];
            #pragma unroll
            for (int p = 0; p < 4; p++)
                v2[p] = *(const u64*)(Vs + c * 128 + 2 * (tx + 16 * p));
            #pragma unroll
            for (int r = 0; r < 4; r++) {
                u64 p2 = dup2(Ps[(ty * 4 + r) * 68 + c]);
                #pragma unroll
                for (int p = 0; p < 4; p++)
                    o2[r][p] = ffma2(p2, v2[p], o2[r][p]);
            }
        }
    }

    // Epilogue: O / l  -> g_xo[b, t, h*D + d]
    #pragma unroll
    for (int r = 0; r < 4; r++) {
        float inv = 1.0f / l[r];
        int row = q0 + ty * 4 + r;
        #pragma unroll
        for (int p = 0; p < 4; p++) {
            float2 v = unpk(o2[r][p]);
            v.x *= inv; v.y *= inv;
            *(float2*)(op + (size_t)row * AT_C + 2 * (tx + 16 * p)) = v;
        }
    }
}

// ---------------------------------------------------------------------------
// Launch: 3 projections -> attention -> output projection
// ---------------------------------------------------------------------------
extern "C" void kernel_launch(void* const* d_in, const int* in_sizes, int n_in,
                              void* d_out, int out_size)
{
    const float* q   = (const float*)d_in[0];
    const float* k   = (const float*)d_in[1];
    const float* v   = (const float*)d_in[2];
    const float* ipw = (const float*)d_in[3];  // (3072, 2048)
    const float* ipb = (const float*)d_in[4];  // (3072,)
    const float* opw = (const float*)d_in[5];  // (2048, 2048)
    const float* opb = (const float*)d_in[6];  // (2048,)
    float* out = (float*)d_out;

    float *xq, *xk, *xv, *xo;
    cudaGetSymbolAddress((void**)&xq, g_xq);
    cudaGetSymbolAddress((void**)&xk, g_xk);
    cudaGetSymbolAddress((void**)&xv, g_xv);
    cudaGetSymbolAddress((void**)&xo, g_xo);

    const int attn_smem = (2 * 64 * 130 + 64 * 128 + 64 * 68) * (int)sizeof(float);  // 116736
    cudaFuncSetAttribute(attn_kernel, cudaFuncAttributeMaxDynamicSharedMemorySize, attn_smem);

    dim3 blk(256);
    const int M_BLK = (AT_B * AT_T) / 128;  // 64

    // xq = query @ Wq^T + bq   (M=8192, N=2048, K=2048)
    gemm_bias_kernel<<<dim3(AT_C / 128, M_BLK), blk>>>(q, ipw, ipb, xq, AT_C, AT_C);
    // xk = key @ Wk^T + bk     (N=512)
    gemm_bias_kernel<<<dim3(AT_KV / 128, M_BLK), blk>>>(
        k, ipw + (size_t)AT_C * AT_C, ipb + AT_C, xk, AT_KV, AT_C);
    // xv = value @ Wv^T + bv   (N=512)
    gemm_bias_kernel<<<dim3(AT_KV / 128, M_BLK), blk>>>(
        v, ipw + (size_t)(AT_C + AT_KV) * AT_C, ipb + AT_C + AT_KV, xv, AT_KV, AT_C);

    // causal GQA flash attention: grid (T/64 query blocks, B*H)
    attn_kernel<<<dim3(AT_T / 64, AT_B * AT_H), blk, attn_smem>>>();

    // out = xo @ Wo^T + bo
    gemm_bias_kernel<<<dim3(AT_C / 128, M_BLK), blk>>>(xo, opw, opb, out, AT_C, AT_C);
}

// round 8
// speedup vs baseline: 1.2893x; 1.2893x over previous
#include <cuda_runtime.h>
#include <cuda_bf16.h>
#include <cstdint>
#include <cstddef>

// Problem constants: B=4, T=2048, C=2048, H=16, G=4, HKV=4, D=128, KV=512
#define AT_B   4
#define AT_T   2048
#define AT_C   2048
#define AT_KV  512
#define AT_D   128
#define AT_H   16
#define AT_HKV 4
#define AT_SCALE 0.08838834764831845f  // 1/sqrt(128)

typedef unsigned long long u64;
typedef unsigned int u32;

// ---------------------------------------------------------------------------
// Packed fp32x2 helpers (sm_103a)
// ---------------------------------------------------------------------------
__device__ __forceinline__ u64 ffma2(u64 a, u64 b, u64 c) {
    u64 d;
    asm("fma.rn.f32x2 %0, %1, %2, %3;" : "=l"(d) : "l"(a), "l"(b), "l"(c));
    return d;
}
__device__ __forceinline__ u64 fmul2(u64 a, u64 b) {
    u64 d;
    asm("mul.rn.f32x2 %0, %1, %2;" : "=l"(d) : "l"(a), "l"(b));
    return d;
}
__device__ __forceinline__ u64 dup2(float x) {
    u64 r;
    asm("mov.b64 %0, {%1, %1};" : "=l"(r) : "f"(x));
    return r;
}
__device__ __forceinline__ float2 unpk(u64 v) {
    float2 r;
    asm("mov.b64 {%0, %1}, %2;" : "=f"(r.x), "=f"(r.y) : "l"(v));
    return r;
}

// ---------------------------------------------------------------------------
// Tensor-core helpers (legacy mma path; fragment layouts per PTX ISA)
// ---------------------------------------------------------------------------
__device__ __forceinline__ void ldsm4(u32* r, u32 addr) {
    asm volatile("ldmatrix.sync.aligned.m8n8.x4.shared.b16 {%0,%1,%2,%3}, [%4];"
                 : "=r"(r[0]), "=r"(r[1]), "=r"(r[2]), "=r"(r[3]) : "r"(addr));
}
__device__ __forceinline__ void mma_bf16(float* d, const u32* a, u32 b0, u32 b1) {
    asm volatile("mma.sync.aligned.m16n8k16.row.col.f32.bf16.bf16.f32 "
                 "{%0,%1,%2,%3}, {%4,%5,%6,%7}, {%8,%9}, {%0,%1,%2,%3};"
                 : "+f"(d[0]), "+f"(d[1]), "+f"(d[2]), "+f"(d[3])
                 : "r"(a[0]), "r"(a[1]), "r"(a[2]), "r"(a[3]), "r"(b0), "r"(b1));
}

// ---------------------------------------------------------------------------
// Scratch (allocation-free rule: __device__ globals)
// ---------------------------------------------------------------------------
__device__ float g_xq[AT_B * AT_T * AT_C];    // 64 MB (attention reads fp32)
__device__ float g_xk[AT_B * AT_T * AT_KV];   // 16 MB
__device__ float g_xv[AT_B * AT_T * AT_KV];   // 16 MB

// bf16 hi/lo splits for tensor-core GEMM operands
__device__ __nv_bfloat16 g_qh[AT_B * AT_T * AT_C], g_ql[AT_B * AT_T * AT_C];
__device__ __nv_bfloat16 g_kh[AT_B * AT_T * AT_C], g_kl[AT_B * AT_T * AT_C];
__device__ __nv_bfloat16 g_vh[AT_B * AT_T * AT_C], g_vl[AT_B * AT_T * AT_C];
__device__ __nv_bfloat16 g_wih[(AT_C + 2 * AT_KV) * AT_C], g_wil[(AT_C + 2 * AT_KV) * AT_C];
__device__ __nv_bfloat16 g_woh[AT_C * AT_C], g_wol[AT_C * AT_C];
__device__ __nv_bfloat16 g_xoh[AT_B * AT_T * AT_C], g_xol[AT_B * AT_T * AT_C];

// ---------------------------------------------------------------------------
// fp32 -> (bf16 hi, bf16 lo) split.  x = hi + lo + O(2^-17 |x|)
// ---------------------------------------------------------------------------
__global__ void split_kernel(const float4* __restrict__ src,
                             uint2* __restrict__ hi, uint2* __restrict__ lo, int n4)
{
    for (int i = blockIdx.x * blockDim.x + threadIdx.x; i < n4; i += gridDim.x * blockDim.x) {
        float4 v = src[i];
        __nv_bfloat162 h01 = __float22bfloat162_rn(make_float2(v.x, v.y));
        __nv_bfloat162 h23 = __float22bfloat162_rn(make_float2(v.z, v.w));
        float l0 = v.x - __low2float(h01),  l1 = v.y - __high2float(h01);
        float l2 = v.z - __low2float(h23),  l3 = v.w - __high2float(h23);
        __nv_bfloat162 l01 = __float22bfloat162_rn(make_float2(l0, l1));
        __nv_bfloat162 l23 = __float22bfloat162_rn(make_float2(l2, l3));
        uint2 hv, lv;
        hv.x = *reinterpret_cast<const u32*>(&h01);
        hv.y = *reinterpret_cast<const u32*>(&h23);
        lv.x = *reinterpret_cast<const u32*>(&l01);
        lv.y = *reinterpret_cast<const u32*>(&l23);
        hi[i] = hv;
        lo[i] = lv;
    }
}

// ---------------------------------------------------------------------------
// bf16x3 tensor-core GEMM: out[M,N] = (Ah+Al)[M,K] @ (Wh+Wl)[N,K]^T + bias[N]
// (dropping the Al*Wl term; fp32 accumulation).
// Block tile 128x128, BK=16, 256 threads, 8 warps of 64x32 warp-tiles.
// Double-buffered smem; rows padded to 24 bf16 (48 B: 16B-aligned,
// conflict-free for ldmatrix phases). Requires M%128==0, N%128==0, K%16==0.
// ---------------------------------------------------------------------------
__global__ __launch_bounds__(256)
void gemm_bf16x3(const __nv_bfloat16* __restrict__ Ahi, const __nv_bfloat16* __restrict__ Alo,
                 const __nv_bfloat16* __restrict__ Whi, const __nv_bfloat16* __restrict__ Wlo,
                 const float* __restrict__ bias, float* __restrict__ out, int N, int K)
{
    // [buf][arr(AH,AL,BH,BL)][row 128][k 24] bf16 = 49152 bytes
    __shared__ __align__(16) __nv_bfloat16 sm[2 * 4 * 128 * 24];
    const u32 ARR = 128 * 48;       // array stride bytes
    const u32 BUF = 4 * ARR;        // buffer stride bytes
    const u32 smem_base = (u32)__cvta_generic_to_shared(sm);

    const int tid  = threadIdx.x;
    const int lrow = tid >> 1;           // 0..127
    const int kh   = (tid & 1) << 3;     // 0 or 8
    const size_t arow = (size_t)(blockIdx.y * 128 + lrow) * K + kh;
    const size_t wrow = (size_t)(blockIdx.x * 128 + lrow) * K + kh;
    const u32 st_off = (u32)(lrow * 48 + kh * 2);

    // preload tile 0
    uint4 va_h = *(const uint4*)(Ahi + arow);
    uint4 va_l = *(const uint4*)(Alo + arow);
    uint4 vw_h = *(const uint4*)(Whi + wrow);
    uint4 vw_l = *(const uint4*)(Wlo + wrow);
    {
        u32 a0 = smem_base + st_off;
        asm volatile("st.shared.v4.b32 [%0], {%1,%2,%3,%4};" :: "r"(a0),           "r"(va_h.x), "r"(va_h.y), "r"(va_h.z), "r"(va_h.w));
        asm volatile("st.shared.v4.b32 [%0], {%1,%2,%3,%4};" :: "r"(a0 + ARR),     "r"(va_l.x), "r"(va_l.y), "r"(va_l.z), "r"(va_l.w));
        asm volatile("st.shared.v4.b32 [%0], {%1,%2,%3,%4};" :: "r"(a0 + 2 * ARR), "r"(vw_h.x), "r"(vw_h.y), "r"(vw_h.z), "r"(vw_h.w));
        asm volatile("st.shared.v4.b32 [%0], {%1,%2,%3,%4};" :: "r"(a0 + 3 * ARR), "r"(vw_l.x), "r"(vw_l.y), "r"(vw_l.z), "r"(vw_l.w));
    }
    __syncthreads();

    const int wid  = tid >> 5, lane = tid & 31;
    const int wm   = (wid & 1) << 6;     // warp m offset (0/64)
    const int wn   = (wid >> 1) << 5;    // warp n offset (0/32/64/96)

    // ldmatrix lane-address offsets (bytes within an array)
    // A frag mf: matrices {rows+0 k0-7, rows+8 k0-7, rows+0 k8-15, rows+8 k8-15}
    const u32 a_off = (u32)((wm + (lane & 7) + ((lane >> 3) & 1) * 8) * 48 + (lane >> 4) * 16);
    // B pair pf (two n8 frags): matrices {n+0 k0-7, n+0 k8-15, n+8 k0-7, n+8 k8-15}
    const u32 b_off = (u32)((wn + (lane & 7) + (lane >> 4) * 8) * 48 + ((lane >> 3) & 1) * 16);

    float acc[4][4][4] = {};

    const int nk = K >> 4;
    int buf = 0;
    for (int kt = 0; kt < nk; kt++) {
        if (kt + 1 < nk) {
            va_h = *(const uint4*)(Ahi + arow + (size_t)(kt + 1) * 16);
            va_l = *(const uint4*)(Alo + arow + (size_t)(kt + 1) * 16);
            vw_h = *(const uint4*)(Whi + wrow + (size_t)(kt + 1) * 16);
            vw_l = *(const uint4*)(Wlo + wrow + (size_t)(kt + 1) * 16);
        }

        u32 ah[4][4], al[4][4], bh[2][4], bl[2][4];
        const u32 base = smem_base + (u32)buf * BUF;
        #pragma unroll
        for (int mf = 0; mf < 4; mf++) {
            u32 addr = base + a_off + mf * 768;   // 16*48
            ldsm4(ah[mf], addr);
            ldsm4(al[mf], addr + ARR);
        }
        #pragma unroll
        for (int pf = 0; pf < 2; pf++) {
            u32 addr = base + 2 * ARR + b_off + pf * 768;
            ldsm4(bh[pf], addr);
            ldsm4(bl[pf], addr + ARR);
        }

        // pass 1: Al * Bh
        #pragma unroll
        for (int mf = 0; mf < 4; mf++)
            #pragma unroll
            for (int nf = 0; nf < 4; nf++)
                mma_bf16(acc[mf][nf], al[mf], bh[nf >> 1][(nf & 1) * 2], bh[nf >> 1][(nf & 1) * 2 + 1]);
        // pass 2: Ah * Bl
        #pragma unroll
        for (int mf = 0; mf < 4; mf++)
            #pragma unroll
            for (int nf = 0; nf < 4; nf++)
                mma_bf16(acc[mf][nf], ah[mf], bl[nf >> 1][(nf & 1) * 2], bl[nf >> 1][(nf & 1) * 2 + 1]);
        // pass 3: Ah * Bh
        #pragma unroll
        for (int mf = 0; mf < 4; mf++)
            #pragma unroll
            for (int nf = 0; nf < 4; nf++)
                mma_bf16(acc[mf][nf], ah[mf], bh[nf >> 1][(nf & 1) * 2], bh[nf >> 1][(nf & 1) * 2 + 1]);

        buf ^= 1;
        if (kt + 1 < nk) {
            u32 a0 = smem_base + (u32)buf * BUF + st_off;
            asm volatile("st.shared.v4.b32 [%0], {%1,%2,%3,%4};" :: "r"(a0),           "r"(va_h.x), "r"(va_h.y), "r"(va_h.z), "r"(va_h.w));
            asm volatile("st.shared.v4.b32 [%0], {%1,%2,%3,%4};" :: "r"(a0 + ARR),     "r"(va_l.x), "r"(va_l.y), "r"(va_l.z), "r"(va_l.w));
            asm volatile("st.shared.v4.b32 [%0], {%1,%2,%3,%4};" :: "r"(a0 + 2 * ARR), "r"(vw_h.x), "r"(vw_h.y), "r"(vw_h.z), "r"(vw_h.w));
            asm volatile("st.shared.v4.b32 [%0], {%1,%2,%3,%4};" :: "r"(a0 + 3 * ARR), "r"(vw_l.x), "r"(vw_l.y), "r"(vw_l.z), "r"(vw_l.w));
        }
        __syncthreads();
    }

    // Epilogue: D fragment c0/c1 -> (row, col..col+1), c2/c3 -> (row+8, ...)
    const int gr  = lane >> 2;
    const int gc2 = (lane & 3) * 2;
    #pragma unroll
    for (int mf = 0; mf < 4; mf++) {
        int row0 = blockIdx.y * 128 + wm + mf * 16 + gr;
        #pragma unroll
        for (int nf = 0; nf < 4; nf++) {
            int col = blockIdx.x * 128 + wn + nf * 8 + gc2;
            float2 bv = *(const float2*)(bias + col);
            float2 o0 = make_float2(acc[mf][nf][0] + bv.x, acc[mf][nf][1] + bv.y);
            float2 o1 = make_float2(acc[mf][nf][2] + bv.x, acc[mf][nf][3] + bv.y);
            *(float2*)(out + (size_t)row0 * N + col)       = o0;
            *(float2*)(out + (size_t)(row0 + 8) * N + col) = o1;
        }
    }
}

// ---------------------------------------------------------------------------
// Flash attention (causal, GQA) — fp32 f32x2 path (unchanged from R4 except
// the epilogue now emits bf16 hi/lo directly for the output projection).
// ---------------------------------------------------------------------------
__global__ __launch_bounds__(256, 1)
void attn_kernel()
{
    extern __shared__ float smem[];
    float* Qs = smem;                    // [64][130]
    float* Ks = smem + 64 * 130;         // [64][130]
    float* Vs = smem + 2 * 64 * 130;     // [64][128]
    float* Ps = Vs + 64 * 128;           // [64][68]

    const int tid = threadIdx.x;
    const int tx = tid & 15, ty = tid >> 4;
    const int qb  = (AT_T / 64 - 1) - blockIdx.x;  // heavy blocks first
    const int bh  = blockIdx.y;
    const int b   = bh >> 4;
    const int hd  = bh & 15;
    const int hkv = hd & 3;

    const float* qp = g_xq + (size_t)b * AT_T * AT_C  + hd  * AT_D;
    const float* kp = g_xk + (size_t)b * AT_T * AT_KV + hkv * AT_D;
    const float* vp = g_xv + (size_t)b * AT_T * AT_KV + hkv * AT_D;
    __nv_bfloat16* oph = g_xoh + (size_t)b * AT_T * AT_C + hd * AT_D;
    __nv_bfloat16* opl = g_xol + (size_t)b * AT_T * AT_C + hd * AT_D;

    const int q0 = qb * 64;

    for (int i = tid; i < 64 * 32; i += 256) {
        int row = i >> 5, c4 = (i & 31) << 2;
        float4 v = *(const float4*)(qp + (size_t)(q0 + row) * AT_C + c4);
        float* dst = Qs + row * 130 + c4;
        dst[0] = v.x; dst[1] = v.y; dst[2] = v.z; dst[3] = v.w;
    }

    float m[4], l[4];
    u64 o2[4][4];
    #pragma unroll
    for (int r = 0; r < 4; r++) {
        m[r] = -1e30f; l[r] = 0.f;
        #pragma unroll
        for (int p = 0; p < 4; p++) o2[r][p] = 0ull;
    }

    for (int j = 0; j <= qb; j++) {
        __syncthreads();
        for (int i = tid; i < 64 * 32; i += 256) {
            int row = i >> 5, c4 = (i & 31) << 2;
            const size_t off = (size_t)(j * 64 + row) * AT_KV + c4;
            float4 kv = *(const float4*)(kp + off);
            float4 vv = *(const float4*)(vp + off);
            float* kd = Ks + row * 130 + c4;
            kd[0] = kv.x; kd[1] = kv.y; kd[2] = kv.z; kd[3] = kv.w;
            *(float4*)(Vs + row * 128 + c4) = vv;
        }
        __syncthreads();

        u64 s2[4][4];
        #pragma unroll
        for (int r = 0; r < 4; r++)
            #pragma unroll
            for (int c = 0; c < 4; c++) s2[r][c] = 0ull;

        #pragma unroll 4
        for (int d = 0; d < 128; d += 2) {
            u64 q2[4], k2[4];
            #pragma unroll
            for (int r = 0; r < 4; r++)
                q2[r] = *(const u64*)(Qs + (ty * 4 + r) * 130 + d);
            #pragma unroll
            for (int c = 0; c < 4; c++)
                k2[c] = *(const u64*)(Ks + (tx + 16 * c) * 130 + d);
            #pragma unroll
            for (int r = 0; r < 4; r++)
                #pragma unroll
                for (int c = 0; c < 4; c++)
                    s2[r][c] = ffma2(q2[r], k2[c], s2[r][c]);
        }

        #pragma unroll
        for (int r = 0; r < 4; r++) {
            const int row = ty * 4 + r;
            const int qi  = q0 + row;
            float s[4];
            #pragma unroll
            for (int c = 0; c < 4; c++) {
                float2 p = unpk(s2[r][c]);
                s[c] = (p.x + p.y) * AT_SCALE;
                if (j * 64 + tx + 16 * c > qi) s[c] = -1e30f;
            }
            float mx = fmaxf(fmaxf(s[0], s[1]), fmaxf(s[2], s[3]));
            #pragma unroll
            for (int off = 8; off > 0; off >>= 1)
                mx = fmaxf(mx, __shfl_xor_sync(0xffffffffu, mx, off));
            float newm = fmaxf(m[r], mx);
            float corr = __expf(m[r] - newm);
            float rs = 0.f;
            #pragma unroll
            for (int c = 0; c < 4; c++) {
                float p = __expf(s[c] - newm);
                Ps[row * 68 + tx + 16 * c] = p;
                rs += p;
            }
            #pragma unroll
            for (int off = 8; off > 0; off >>= 1)
                rs += __shfl_xor_sync(0xffffffffu, rs, off);
            l[r] = l[r] * corr + rs;
            m[r] = newm;
            u64 c2 = dup2(corr);
            #pragma unroll
            for (int p = 0; p < 4; p++) o2[r][p] = fmul2(o2[r][p], c2);
        }
        __syncthreads();

        #pragma unroll 2
        for (int c = 0; c < 64; c++) {
            u64 v2[4];
            #pragma unroll
            for (int p = 0; p < 4; p++)
                v2[p] = *(const u64*)(Vs + c * 128 + 2 * (tx + 16 * p));
            #pragma unroll
            for (int r = 0; r < 4; r++) {
                u64 p2 = dup2(Ps[(ty * 4 + r) * 68 + c]);
                #pragma unroll
                for (int p = 0; p < 4; p++)
                    o2[r][p] = ffma2(p2, v2[p], o2[r][p]);
            }
        }
    }

    // Epilogue: O/l -> bf16 hi/lo split (out-projection GEMM operand)
    #pragma unroll
    for (int r = 0; r < 4; r++) {
        float inv = 1.0f / l[r];
        int row = q0 + ty * 4 + r;
        #pragma unroll
        for (int p = 0; p < 4; p++) {
            float2 v = unpk(o2[r][p]);
            v.x *= inv; v.y *= inv;
            __nv_bfloat162 hv = __float22bfloat162_rn(v);
            float lx = v.x - __low2float(hv);
            float ly = v.y - __high2float(hv);
            __nv_bfloat162 lv = __float22bfloat162_rn(make_float2(lx, ly));
            size_t idx = (size_t)row * AT_C + 2 * (tx + 16 * p);
            *(__nv_bfloat162*)(oph + idx) = hv;
            *(__nv_bfloat162*)(opl + idx) = lv;
        }
    }
}

// ---------------------------------------------------------------------------
// Launch: split prep -> 3 projections -> attention -> output projection
// ---------------------------------------------------------------------------
extern "C" void kernel_launch(void* const* d_in, const int* in_sizes, int n_in,
                              void* d_out, int out_size)
{
    const float* q   = (const float*)d_in[0];
    const float* k   = (const float*)d_in[1];
    const float* v   = (const float*)d_in[2];
    const float* ipw = (const float*)d_in[3];  // (3072, 2048)
    const float* ipb = (const float*)d_in[4];  // (3072,)
    const float* opw = (const float*)d_in[5];  // (2048, 2048)
    const float* opb = (const float*)d_in[6];  // (2048,)
    float* out = (float*)d_out;

    float *xq, *xk, *xv;
    cudaGetSymbolAddress((void**)&xq, g_xq);
    cudaGetSymbolAddress((void**)&xk, g_xk);
    cudaGetSymbolAddress((void**)&xv, g_xv);

    __nv_bfloat16 *qh, *ql, *kh, *kl, *vh, *vl, *wih, *wil, *woh, *wol, *xoh, *xol;
    cudaGetSymbolAddress((void**)&qh, g_qh);   cudaGetSymbolAddress((void**)&ql, g_ql);
    cudaGetSymbolAddress((void**)&kh, g_kh);   cudaGetSymbolAddress((void**)&kl, g_kl);
    cudaGetSymbolAddress((void**)&vh, g_vh);   cudaGetSymbolAddress((void**)&vl, g_vl);
    cudaGetSymbolAddress((void**)&wih, g_wih); cudaGetSymbolAddress((void**)&wil, g_wil);
    cudaGetSymbolAddress((void**)&woh, g_woh); cudaGetSymbolAddress((void**)&wol, g_wol);
    cudaGetSymbolAddress((void**)&xoh, g_xoh); cudaGetSymbolAddress((void**)&xol, g_xol);

    const int attn_smem = (2 * 64 * 130 + 64 * 128 + 64 * 68) * (int)sizeof(float);  // 116736
    cudaFuncSetAttribute(attn_kernel, cudaFuncAttributeMaxDynamicSharedMemorySize, attn_smem);

    dim3 blk(256);
    const int M_BLK = (AT_B * AT_T) / 128;  // 64

    // Prep: split inputs + weights into bf16 hi/lo
    const int n_act  = AT_B * AT_T * AT_C / 4;                 // float4 count
    const int n_ipw  = (AT_C + 2 * AT_KV) * AT_C / 4;
    const int n_opw  = AT_C * AT_C / 4;
    split_kernel<<<4096, 256>>>((const float4*)q,   (uint2*)qh,  (uint2*)ql,  n_act);
    split_kernel<<<4096, 256>>>((const float4*)k,   (uint2*)kh,  (uint2*)kl,  n_act);
    split_kernel<<<4096, 256>>>((const float4*)v,   (uint2*)vh,  (uint2*)vl,  n_act);
    split_kernel<<<4096, 256>>>((const float4*)ipw, (uint2*)wih, (uint2*)wil, n_ipw);
    split_kernel<<<4096, 256>>>((const float4*)opw, (uint2*)woh, (uint2*)wol, n_opw);

    // Projections (tensor-core bf16x3)
    gemm_bf16x3<<<dim3(AT_C / 128, M_BLK), blk>>>(qh, ql, wih, wil, ipb, xq, AT_C, AT_C);
    gemm_bf16x3<<<dim3(AT_KV / 128, M_BLK), blk>>>(
        kh, kl, wih + (size_t)AT_C * AT_C, wil + (size_t)AT_C * AT_C,
        ipb + AT_C, xk, AT_KV, AT_C);
    gemm_bf16x3<<<dim3(AT_KV / 128, M_BLK), blk>>>(
        vh, vl, wih + (size_t)(AT_C + AT_KV) * AT_C, wil + (size_t)(AT_C + AT_KV) * AT_C,
        ipb + AT_C + AT_KV, xv, AT_KV, AT_C);

    // Causal GQA flash attention (writes xo hi/lo)
    attn_kernel<<<dim3(AT_T / 64, AT_B * AT_H), blk, attn_smem>>>();

    // Output projection
    gemm_bf16x3<<<dim3(AT_C / 128, M_BLK), blk>>>(xoh, xol, woh, wol, opb, out, AT_C, AT_C);
}

// round 9
// speedup vs baseline: 2.0351x; 1.5784x over previous
#include <cuda_runtime.h>
#include <cuda_bf16.h>
#include <cstdint>
#include <cstddef>

// Problem constants: B=4, T=2048, C=2048, H=16, G=4, HKV=4, D=128, KV=512
#define AT_B   4
#define AT_T   2048
#define AT_C   2048
#define AT_KV  512
#define AT_D   128
#define AT_H   16
#define AT_HKV 4
#define AT_SCALE 0.08838834764831845f  // 1/sqrt(128)

typedef unsigned long long u64;
typedef unsigned int u32;

// ---------------------------------------------------------------------------
// Tensor-core helpers (legacy mma path; fragment layouts per PTX ISA)
// ---------------------------------------------------------------------------
__device__ __forceinline__ void ldsm4(u32* r, u32 addr) {
    asm volatile("ldmatrix.sync.aligned.m8n8.x4.shared.b16 {%0,%1,%2,%3}, [%4];"
                 : "=r"(r[0]), "=r"(r[1]), "=r"(r[2]), "=r"(r[3]) : "r"(addr));
}
__device__ __forceinline__ void ldsm4t(u32* r, u32 addr) {
    asm volatile("ldmatrix.sync.aligned.m8n8.x4.trans.shared.b16 {%0,%1,%2,%3}, [%4];"
                 : "=r"(r[0]), "=r"(r[1]), "=r"(r[2]), "=r"(r[3]) : "r"(addr));
}
__device__ __forceinline__ void mma_bf16(float* d, const u32* a, u32 b0, u32 b1) {
    asm volatile("mma.sync.aligned.m16n8k16.row.col.f32.bf16.bf16.f32 "
                 "{%0,%1,%2,%3}, {%4,%5,%6,%7}, {%8,%9}, {%0,%1,%2,%3};"
                 : "+f"(d[0]), "+f"(d[1]), "+f"(d[2]), "+f"(d[3])
                 : "r"(a[0]), "r"(a[1]), "r"(a[2]), "r"(a[3]), "r"(b0), "r"(b1));
}

__device__ __forceinline__ void pack2hl(float x, float y, u32& h, u32& l) {
    __nv_bfloat162 hv = __float22bfloat162_rn(make_float2(x, y));
    float lx = x - __low2float(hv), ly = y - __high2float(hv);
    __nv_bfloat162 lv = __float22bfloat162_rn(make_float2(lx, ly));
    h = *reinterpret_cast<u32*>(&hv);
    l = *reinterpret_cast<u32*>(&lv);
}

// ---------------------------------------------------------------------------
// Scratch (allocation-free rule: __device__ globals)
// ---------------------------------------------------------------------------
// bf16 hi/lo splits of the fp32 inputs / weights
__device__ __nv_bfloat16 g_qh[AT_B * AT_T * AT_C], g_ql[AT_B * AT_T * AT_C];
__device__ __nv_bfloat16 g_kh[AT_B * AT_T * AT_C], g_kl[AT_B * AT_T * AT_C];
__device__ __nv_bfloat16 g_vh[AT_B * AT_T * AT_C], g_vl[AT_B * AT_T * AT_C];
__device__ __nv_bfloat16 g_wih[(AT_C + 2 * AT_KV) * AT_C], g_wil[(AT_C + 2 * AT_KV) * AT_C];
__device__ __nv_bfloat16 g_woh[AT_C * AT_C], g_wol[AT_C * AT_C];
// projection outputs (bf16 hi/lo) — consumed by tensor-core attention
__device__ __nv_bfloat16 g_xqh[AT_B * AT_T * AT_C],  g_xql[AT_B * AT_T * AT_C];
__device__ __nv_bfloat16 g_xkh[AT_B * AT_T * AT_KV], g_xkl[AT_B * AT_T * AT_KV];
__device__ __nv_bfloat16 g_xvh[AT_B * AT_T * AT_KV], g_xvl[AT_B * AT_T * AT_KV];
// attention output (bf16 hi/lo) — consumed by out-projection
__device__ __nv_bfloat16 g_xoh[AT_B * AT_T * AT_C], g_xol[AT_B * AT_T * AT_C];

// ---------------------------------------------------------------------------
// fp32 -> (bf16 hi, bf16 lo) split.  x = hi + lo + O(2^-17 |x|)
// ---------------------------------------------------------------------------
__global__ void split_kernel(const float4* __restrict__ src,
                             uint2* __restrict__ hi, uint2* __restrict__ lo, int n4)
{
    for (int i = blockIdx.x * blockDim.x + threadIdx.x; i < n4; i += gridDim.x * blockDim.x) {
        float4 v = src[i];
        u32 h0, l0, h1, l1;
        pack2hl(v.x, v.y, h0, l0);
        pack2hl(v.z, v.w, h1, l1);
        hi[i] = make_uint2(h0, h1);
        lo[i] = make_uint2(l0, l1);
    }
}

// ---------------------------------------------------------------------------
// bf16x3 tensor-core GEMM: out[M,N] = (Ah+Al)[M,K] @ (Wh+Wl)[N,K]^T + bias[N]
// SPLIT=false: fp32 output.  SPLIT=true: bf16 hi/lo split output.
// ---------------------------------------------------------------------------
template<bool SPLIT>
__global__ __launch_bounds__(256)
void gemm_bf16x3(const __nv_bfloat16* __restrict__ Ahi, const __nv_bfloat16* __restrict__ Alo,
                 const __nv_bfloat16* __restrict__ Whi, const __nv_bfloat16* __restrict__ Wlo,
                 const float* __restrict__ bias, float* __restrict__ out,
                 __nv_bfloat16* __restrict__ oh, __nv_bfloat16* __restrict__ ol,
                 int N, int K)
{
    __shared__ __align__(16) __nv_bfloat16 sm[2 * 4 * 128 * 24];
    const u32 ARR = 128 * 48;
    const u32 BUF = 4 * ARR;
    const u32 smem_base = (u32)__cvta_generic_to_shared(sm);

    const int tid  = threadIdx.x;
    const int lrow = tid >> 1;
    const int kh   = (tid & 1) << 3;
    const size_t arow = (size_t)(blockIdx.y * 128 + lrow) * K + kh;
    const size_t wrow = (size_t)(blockIdx.x * 128 + lrow) * K + kh;
    const u32 st_off = (u32)(lrow * 48 + kh * 2);

    uint4 va_h = *(const uint4*)(Ahi + arow);
    uint4 va_l = *(const uint4*)(Alo + arow);
    uint4 vw_h = *(const uint4*)(Whi + wrow);
    uint4 vw_l = *(const uint4*)(Wlo + wrow);
    {
        u32 a0 = smem_base + st_off;
        asm volatile("st.shared.v4.b32 [%0], {%1,%2,%3,%4};" :: "r"(a0),           "r"(va_h.x), "r"(va_h.y), "r"(va_h.z), "r"(va_h.w));
        asm volatile("st.shared.v4.b32 [%0], {%1,%2,%3,%4};" :: "r"(a0 + ARR),     "r"(va_l.x), "r"(va_l.y), "r"(va_l.z), "r"(va_l.w));
        asm volatile("st.shared.v4.b32 [%0], {%1,%2,%3,%4};" :: "r"(a0 + 2 * ARR), "r"(vw_h.x), "r"(vw_h.y), "r"(vw_h.z), "r"(vw_h.w));
        asm volatile("st.shared.v4.b32 [%0], {%1,%2,%3,%4};" :: "r"(a0 + 3 * ARR), "r"(vw_l.x), "r"(vw_l.y), "r"(vw_l.z), "r"(vw_l.w));
    }
    __syncthreads();

    const int wid  = tid >> 5, lane = tid & 31;
    const int wm   = (wid & 1) << 6;
    const int wn   = (wid >> 1) << 5;

    const u32 a_off = (u32)((wm + (lane & 7) + ((lane >> 3) & 1) * 8) * 48 + (lane >> 4) * 16);
    const u32 b_off = (u32)((wn + (lane & 7) + (lane >> 4) * 8) * 48 + ((lane >> 3) & 1) * 16);

    float acc[4][4][4] = {};

    const int nk = K >> 4;
    int buf = 0;
    for (int kt = 0; kt < nk; kt++) {
        if (kt + 1 < nk) {
            va_h = *(const uint4*)(Ahi + arow + (size_t)(kt + 1) * 16);
            va_l = *(const uint4*)(Alo + arow + (size_t)(kt + 1) * 16);
            vw_h = *(const uint4*)(Whi + wrow + (size_t)(kt + 1) * 16);
            vw_l = *(const uint4*)(Wlo + wrow + (size_t)(kt + 1) * 16);
        }

        u32 ah[4][4], al[4][4], bh[2][4], bl[2][4];
        const u32 base = smem_base + (u32)buf * BUF;
        #pragma unroll
        for (int mf = 0; mf < 4; mf++) {
            u32 addr = base + a_off + mf * 768;
            ldsm4(ah[mf], addr);
            ldsm4(al[mf], addr + ARR);
        }
        #pragma unroll
        for (int pf = 0; pf < 2; pf++) {
            u32 addr = base + 2 * ARR + b_off + pf * 768;
            ldsm4(bh[pf], addr);
            ldsm4(bl[pf], addr + ARR);
        }

        #pragma unroll
        for (int mf = 0; mf < 4; mf++)
            #pragma unroll
            for (int nf = 0; nf < 4; nf++)
                mma_bf16(acc[mf][nf], al[mf], bh[nf >> 1][(nf & 1) * 2], bh[nf >> 1][(nf & 1) * 2 + 1]);
        #pragma unroll
        for (int mf = 0; mf < 4; mf++)
            #pragma unroll
            for (int nf = 0; nf < 4; nf++)
                mma_bf16(acc[mf][nf], ah[mf], bl[nf >> 1][(nf & 1) * 2], bl[nf >> 1][(nf & 1) * 2 + 1]);
        #pragma unroll
        for (int mf = 0; mf < 4; mf++)
            #pragma unroll
            for (int nf = 0; nf < 4; nf++)
                mma_bf16(acc[mf][nf], ah[mf], bh[nf >> 1][(nf & 1) * 2], bh[nf >> 1][(nf & 1) * 2 + 1]);

        buf ^= 1;
        if (kt + 1 < nk) {
            u32 a0 = smem_base + (u32)buf * BUF + st_off;
            asm volatile("st.shared.v4.b32 [%0], {%1,%2,%3,%4};" :: "r"(a0),           "r"(va_h.x), "r"(va_h.y), "r"(va_h.z), "r"(va_h.w));
            asm volatile("st.shared.v4.b32 [%0], {%1,%2,%3,%4};" :: "r"(a0 + ARR),     "r"(va_l.x), "r"(va_l.y), "r"(va_l.z), "r"(va_l.w));
            asm volatile("st.shared.v4.b32 [%0], {%1,%2,%3,%4};" :: "r"(a0 + 2 * ARR), "r"(vw_h.x), "r"(vw_h.y), "r"(vw_h.z), "r"(vw_h.w));
            asm volatile("st.shared.v4.b32 [%0], {%1,%2,%3,%4};" :: "r"(a0 + 3 * ARR), "r"(vw_l.x), "r"(vw_l.y), "r"(vw_l.z), "r"(vw_l.w));
        }
        __syncthreads();
    }

    const int gr  = lane >> 2;
    const int gc2 = (lane & 3) * 2;
    #pragma unroll
    for (int mf = 0; mf < 4; mf++) {
        int row0 = blockIdx.y * 128 + wm + mf * 16 + gr;
        #pragma unroll
        for (int nf = 0; nf < 4; nf++) {
            int col = blockIdx.x * 128 + wn + nf * 8 + gc2;
            float2 bv = *(const float2*)(bias + col);
            float v00 = acc[mf][nf][0] + bv.x, v01 = acc[mf][nf][1] + bv.y;
            float v10 = acc[mf][nf][2] + bv.x, v11 = acc[mf][nf][3] + bv.y;
            if (SPLIT) {
                u32 h0, l0, h1, l1;
                pack2hl(v00, v01, h0, l0);
                pack2hl(v10, v11, h1, l1);
                *(u32*)(oh + (size_t)row0 * N + col)       = h0;
                *(u32*)(ol + (size_t)row0 * N + col)       = l0;
                *(u32*)(oh + (size_t)(row0 + 8) * N + col) = h1;
                *(u32*)(ol + (size_t)(row0 + 8) * N + col) = l1;
            } else {
                *(float2*)(out + (size_t)row0 * N + col)       = make_float2(v00, v01);
                *(float2*)(out + (size_t)(row0 + 8) * N + col) = make_float2(v10, v11);
            }
        }
    }
}

// ---------------------------------------------------------------------------
// Tensor-core flash attention (causal, GQA), bf16x3 for QK^T and PV.
// Block = 128 q-rows of one (b,h); 8 warps, each owns m16 x n64 of S and
// m16 x n128 of O.  Per kv tile (64 wide): S via mma (Q,K hi/lo from smem),
// register softmax (rows fully warp-owned), P packed from S D-frags directly
// into A-frags (hi/lo), PV via mma with V through ldmatrix.trans.
// ---------------------------------------------------------------------------
__global__ __launch_bounds__(256, 1)
void attn_tc_kernel()
{
    extern __shared__ __align__(16) __nv_bfloat16 smx[];
    // half-offsets; row pitch 136 halves (272 B) -> conflict-free ldmatrix
    __nv_bfloat16* Qh_s = smx;                 // [128][136]
    __nv_bfloat16* Ql_s = smx + 17408;
    __nv_bfloat16* Kh_s = smx + 34816;         // [64][136]
    __nv_bfloat16* Kl_s = smx + 43520;
    __nv_bfloat16* Vh_s = smx + 52224;         // [64][136]
    __nv_bfloat16* Vl_s = smx + 60928;
    const u32 sb  = (u32)__cvta_generic_to_shared(smx);
    const u32 QH = 0, QL = 34816, KH = 69632, KL = 87040, VH = 104448, VL = 121856;

    const int tid  = threadIdx.x;
    const int wid  = tid >> 5, lane = tid & 31;
    const int bh   = blockIdx.x;
    const int b    = bh >> 4;
    const int hd   = bh & 15;
    const int hkv  = hd & 3;
    const int qi   = 15 - blockIdx.y;          // heavy blocks first
    const int q0   = qi * 128;

    const __nv_bfloat16* qhp = g_xqh + ((size_t)b * AT_T + q0) * AT_C + hd * AT_D;
    const __nv_bfloat16* qlp = g_xql + ((size_t)b * AT_T + q0) * AT_C + hd * AT_D;
    const __nv_bfloat16* khp = g_xkh + (size_t)b * AT_T * AT_KV + hkv * AT_D;
    const __nv_bfloat16* klp = g_xkl + (size_t)b * AT_T * AT_KV + hkv * AT_D;
    const __nv_bfloat16* vhp = g_xvh + (size_t)b * AT_T * AT_KV + hkv * AT_D;
    const __nv_bfloat16* vlp = g_xvl + (size_t)b * AT_T * AT_KV + hkv * AT_D;

    // Load Q tile (128 x 128 halves, hi+lo)
    for (int i = tid; i < 2048; i += 256) {
        int row = i >> 4, cc = (i & 15) << 3;
        *(uint4*)(Qh_s + row * 136 + cc) = *(const uint4*)(qhp + (size_t)row * AT_C + cc);
        *(uint4*)(Ql_s + row * 136 + cc) = *(const uint4*)(qlp + (size_t)row * AT_C + cc);
    }

    const int wq = wid * 16;                   // warp's 16 rows within block
    const int gr = lane >> 2;
    const int qrow0 = q0 + wq + gr;            // global q row of D-frag row0
    const int qrow1 = qrow0 + 8;

    const u32 a_off = (u32)((wq + (lane & 7) + ((lane >> 3) & 1) * 8) * 272 + (lane >> 4) * 16);
    const u32 b_off = (u32)(((lane & 7) + (lane >> 4) * 8) * 272 + ((lane >> 3) & 1) * 16);
    const u32 v_off = (u32)(((lane & 7) + ((lane >> 3) & 1) * 8) * 272 + (lane >> 4) * 16);

    float o[16][4];
    #pragma unroll
    for (int nf = 0; nf < 16; nf++)
        #pragma unroll
        for (int k = 0; k < 4; k++) o[nf][k] = 0.f;
    float m0 = -1e30f, m1 = -1e30f, l0 = 0.f, l1 = 0.f;

    const int ntiles = 2 * qi + 2;
    for (int j = 0; j < ntiles; j++) {
        __syncthreads();   // previous tile consumed
        for (int i = tid; i < 1024; i += 256) {
            int row = i >> 4, cc = (i & 15) << 3;
            size_t g = (size_t)(j * 64 + row) * AT_KV + cc;
            *(uint4*)(Kh_s + row * 136 + cc) = *(const uint4*)(khp + g);
            *(uint4*)(Kl_s + row * 136 + cc) = *(const uint4*)(klp + g);
            *(uint4*)(Vh_s + row * 136 + cc) = *(const uint4*)(vhp + g);
            *(uint4*)(Vl_s + row * 136 + cc) = *(const uint4*)(vlp + g);
        }
        __syncthreads();

        // ---- S = Q K^T (bf16x3) ----
        float s[8][4];
        #pragma unroll
        for (int nf = 0; nf < 8; nf++)
            #pragma unroll
            for (int k = 0; k < 4; k++) s[nf][k] = 0.f;

        #pragma unroll
        for (int c = 0; c < 8; c++) {
            u32 ah[4], al[4];
            ldsm4(ah, sb + QH + a_off + c * 32);
            ldsm4(al, sb + QL + a_off + c * 32);
            #pragma unroll
            for (int nb = 0; nb < 4; nb++) {
                u32 bh_[4], bl_[4];
                u32 ka = b_off + nb * 4352 + c * 32;
                ldsm4(bh_, sb + KH + ka);
                ldsm4(bl_, sb + KL + ka);
                mma_bf16(s[2 * nb],     al, bh_[0], bh_[1]);
                mma_bf16(s[2 * nb + 1], al, bh_[2], bh_[3]);
                mma_bf16(s[2 * nb],     ah, bl_[0], bl_[1]);
                mma_bf16(s[2 * nb + 1], ah, bl_[2], bl_[3]);
                mma_bf16(s[2 * nb],     ah, bh_[0], bh_[1]);
                mma_bf16(s[2 * nb + 1], ah, bh_[2], bh_[3]);
            }
        }

        // ---- online softmax (rows warp-owned; quad reductions) ----
        const bool maskt = (j >= 2 * qi);
        const int colb = j * 64 + 2 * (lane & 3);
        float mx0 = -1e30f, mx1 = -1e30f;
        #pragma unroll
        for (int nf = 0; nf < 8; nf++) {
            int c0 = colb + 8 * nf;
            s[nf][0] *= AT_SCALE; s[nf][1] *= AT_SCALE;
            s[nf][2] *= AT_SCALE; s[nf][3] *= AT_SCALE;
            if (maskt) {
                if (c0     > qrow0) s[nf][0] = -1e30f;
                if (c0 + 1 > qrow0) s[nf][1] = -1e30f;
                if (c0     > qrow1) s[nf][2] = -1e30f;
                if (c0 + 1 > qrow1) s[nf][3] = -1e30f;
            }
            mx0 = fmaxf(mx0, fmaxf(s[nf][0], s[nf][1]));
            mx1 = fmaxf(mx1, fmaxf(s[nf][2], s[nf][3]));
        }
        mx0 = fmaxf(mx0, __shfl_xor_sync(0xffffffffu, mx0, 1));
        mx0 = fmaxf(mx0, __shfl_xor_sync(0xffffffffu, mx0, 2));
        mx1 = fmaxf(mx1, __shfl_xor_sync(0xffffffffu, mx1, 1));
        mx1 = fmaxf(mx1, __shfl_xor_sync(0xffffffffu, mx1, 2));

        float nm0 = fmaxf(m0, mx0), nm1 = fmaxf(m1, mx1);
        float corr0 = __expf(m0 - nm0), corr1 = __expf(m1 - nm1);
        m0 = nm0; m1 = nm1;

        float rs0 = 0.f, rs1 = 0.f;
        #pragma unroll
        for (int nf = 0; nf < 8; nf++) {
            s[nf][0] = __expf(s[nf][0] - m0); rs0 += s[nf][0];
            s[nf][1] = __expf(s[nf][1] - m0); rs0 += s[nf][1];
            s[nf][2] = __expf(s[nf][2] - m1); rs1 += s[nf][2];
            s[nf][3] = __expf(s[nf][3] - m1); rs1 += s[nf][3];
        }
        rs0 += __shfl_xor_sync(0xffffffffu, rs0, 1);
        rs0 += __shfl_xor_sync(0xffffffffu, rs0, 2);
        rs1 += __shfl_xor_sync(0xffffffffu, rs1, 1);
        rs1 += __shfl_xor_sync(0xffffffffu, rs1, 2);
        l0 = l0 * corr0 + rs0;
        l1 = l1 * corr1 + rs1;

        #pragma unroll
        for (int nf = 0; nf < 16; nf++) {
            o[nf][0] *= corr0; o[nf][1] *= corr0;
            o[nf][2] *= corr1; o[nf][3] *= corr1;
        }

        // ---- O += P V (bf16x3; P packed directly from S D-frags) ----
        #pragma unroll
        for (int c = 0; c < 4; c++) {
            u32 aph[4], apl[4];
            pack2hl(s[2 * c][0],     s[2 * c][1],     aph[0], apl[0]);
            pack2hl(s[2 * c][2],     s[2 * c][3],     aph[1], apl[1]);
            pack2hl(s[2 * c + 1][0], s[2 * c + 1][1], aph[2], apl[2]);
            pack2hl(s[2 * c + 1][2], s[2 * c + 1][3], aph[3], apl[3]);
            #pragma unroll
            for (int nb = 0; nb < 8; nb++) {
                u32 vh_[4], vl_[4];
                u32 va = v_off + c * 4352 + nb * 32;
                ldsm4t(vh_, sb + VH + va);
                ldsm4t(vl_, sb + VL + va);
                mma_bf16(o[2 * nb],     aph, vh_[0], vh_[1]);
                mma_bf16(o[2 * nb + 1], aph, vh_[2], vh_[3]);
                mma_bf16(o[2 * nb],     aph, vl_[0], vl_[1]);
                mma_bf16(o[2 * nb + 1], aph, vl_[2], vl_[3]);
                mma_bf16(o[2 * nb],     apl, vh_[0], vh_[1]);
                mma_bf16(o[2 * nb + 1], apl, vh_[2], vh_[3]);
            }
        }
    }

    // ---- epilogue: O/l -> bf16 hi/lo (A operand of out-projection) ----
    const float inv0 = 1.0f / l0, inv1 = 1.0f / l1;
    const size_t obase = (size_t)b * AT_T * AT_C + (size_t)hd * AT_D;
    #pragma unroll
    for (int nf = 0; nf < 16; nf++) {
        int d = nf * 8 + 2 * (lane & 3);
        u32 h0, lo0, h1, lo1;
        pack2hl(o[nf][0] * inv0, o[nf][1] * inv0, h0, lo0);
        pack2hl(o[nf][2] * inv1, o[nf][3] * inv1, h1, lo1);
        size_t i0 = obase + (size_t)qrow0 * AT_C + d;
        size_t i1 = obase + (size_t)qrow1 * AT_C + d;
        *(u32*)(g_xoh + i0) = h0;  *(u32*)(g_xol + i0) = lo0;
        *(u32*)(g_xoh + i1) = h1;  *(u32*)(g_xol + i1) = lo1;
    }
}

// ---------------------------------------------------------------------------
// Launch: split prep -> 3 projections (split out) -> TC attention -> out proj
// ---------------------------------------------------------------------------
extern "C" void kernel_launch(void* const* d_in, const int* in_sizes, int n_in,
                              void* d_out, int out_size)
{
    const float* q   = (const float*)d_in[0];
    const float* k   = (const float*)d_in[1];
    const float* v   = (const float*)d_in[2];
    const float* ipw = (const float*)d_in[3];  // (3072, 2048)
    const float* ipb = (const float*)d_in[4];  // (3072,)
    const float* opw = (const float*)d_in[5];  // (2048, 2048)
    const float* opb = (const float*)d_in[6];  // (2048,)
    float* out = (float*)d_out;

    __nv_bfloat16 *qh, *ql, *kh, *kl, *vh, *vl, *wih, *wil, *woh, *wol;
    __nv_bfloat16 *xqh, *xql, *xkh, *xkl, *xvh, *xvl, *xoh, *xol;
    cudaGetSymbolAddress((void**)&qh, g_qh);   cudaGetSymbolAddress((void**)&ql, g_ql);
    cudaGetSymbolAddress((void**)&kh, g_kh);   cudaGetSymbolAddress((void**)&kl, g_kl);
    cudaGetSymbolAddress((void**)&vh, g_vh);   cudaGetSymbolAddress((void**)&vl, g_vl);
    cudaGetSymbolAddress((void**)&wih, g_wih); cudaGetSymbolAddress((void**)&wil, g_wil);
    cudaGetSymbolAddress((void**)&woh, g_woh); cudaGetSymbolAddress((void**)&wol, g_wol);
    cudaGetSymbolAddress((void**)&xqh, g_xqh); cudaGetSymbolAddress((void**)&xql, g_xql);
    cudaGetSymbolAddress((void**)&xkh, g_xkh); cudaGetSymbolAddress((void**)&xkl, g_xkl);
    cudaGetSymbolAddress((void**)&xvh, g_xvh); cudaGetSymbolAddress((void**)&xvl, g_xvl);
    cudaGetSymbolAddress((void**)&xoh, g_xoh); cudaGetSymbolAddress((void**)&xol, g_xol);

    const int attn_smem = 139264;  // bytes: (128+64+64)*136*2 halves, hi+lo
    cudaFuncSetAttribute(attn_tc_kernel, cudaFuncAttributeMaxDynamicSharedMemorySize, attn_smem);

    dim3 blk(256);
    const int M_BLK = (AT_B * AT_T) / 128;  // 64

    // Prep: split inputs + weights into bf16 hi/lo
    const int n_act = AT_B * AT_T * AT_C / 4;
    const int n_ipw = (AT_C + 2 * AT_KV) * AT_C / 4;
    const int n_opw = AT_C * AT_C / 4;
    split_kernel<<<4096, 256>>>((const float4*)q,   (uint2*)qh,  (uint2*)ql,  n_act);
    split_kernel<<<4096, 256>>>((const float4*)k,   (uint2*)kh,  (uint2*)kl,  n_act);
    split_kernel<<<4096, 256>>>((const float4*)v,   (uint2*)vh,  (uint2*)vl,  n_act);
    split_kernel<<<4096, 256>>>((const float4*)ipw, (uint2*)wih, (uint2*)wil, n_ipw);
    split_kernel<<<4096, 256>>>((const float4*)opw, (uint2*)woh, (uint2*)wol, n_opw);

    // Projections: bf16x3 tensor-core GEMMs, split bf16 hi/lo outputs
    gemm_bf16x3<true><<<dim3(AT_C / 128, M_BLK), blk>>>(
        qh, ql, wih, wil, ipb, nullptr, xqh, xql, AT_C, AT_C);
    gemm_bf16x3<true><<<dim3(AT_KV / 128, M_BLK), blk>>>(
        kh, kl, wih + (size_t)AT_C * AT_C, wil + (size_t)AT_C * AT_C,
        ipb + AT_C, nullptr, xkh, xkl, AT_KV, AT_C);
    gemm_bf16x3<true><<<dim3(AT_KV / 128, M_BLK), blk>>>(
        vh, vl, wih + (size_t)(AT_C + AT_KV) * AT_C, wil + (size_t)(AT_C + AT_KV) * AT_C,
        ipb + AT_C + AT_KV, nullptr, xvh, xvl, AT_KV, AT_C);

    // Tensor-core causal GQA flash attention
    attn_tc_kernel<<<dim3(AT_B * AT_H, AT_T / 128), blk, attn_smem>>>();

    // Output projection (fp32 out)
    gemm_bf16x3<false><<<dim3(AT_C / 128, M_BLK), blk>>>(
        xoh, xol, woh, wol, opb, out, nullptr, nullptr, AT_C, AT_C);
}

// round 11
// speedup vs baseline: 2.5493x; 1.2527x over previous
#include <cuda_runtime.h>
#include <cuda_bf16.h>
#include <cstdint>
#include <cstddef>

// Problem constants: B=4, T=2048, C=2048, H=16, G=4, HKV=4, D=128, KV=512
#define AT_B   4
#define AT_T   2048
#define AT_C   2048
#define AT_KV  512
#define AT_D   128
#define AT_H   16
#define AT_HKV 4
#define AT_SCALE 0.08838834764831845f  // 1/sqrt(128)

typedef unsigned long long u64;
typedef unsigned int u32;

// ---------------------------------------------------------------------------
// Common helpers
// ---------------------------------------------------------------------------
__device__ __forceinline__ void pack2hl(float x, float y, u32& h, u32& l) {
    __nv_bfloat162 hv = __float22bfloat162_rn(make_float2(x, y));
    float lx = x - __low2float(hv), ly = y - __high2float(hv);
    __nv_bfloat162 lv = __float22bfloat162_rn(make_float2(lx, ly));
    h = *reinterpret_cast<u32*>(&hv);
    l = *reinterpret_cast<u32*>(&lv);
}

// ---- legacy mma helpers (proven in R8/R9) ----
__device__ __forceinline__ void ldsm4(u32* r, u32 addr) {
    asm volatile("ldmatrix.sync.aligned.m8n8.x4.shared.b16 {%0,%1,%2,%3}, [%4];"
                 : "=r"(r[0]), "=r"(r[1]), "=r"(r[2]), "=r"(r[3]) : "r"(addr));
}
__device__ __forceinline__ void ldsm4t(u32* r, u32 addr) {
    asm volatile("ldmatrix.sync.aligned.m8n8.x4.trans.shared.b16 {%0,%1,%2,%3}, [%4];"
                 : "=r"(r[0]), "=r"(r[1]), "=r"(r[2]), "=r"(r[3]) : "r"(addr));
}
__device__ __forceinline__ void mma_bf16(float* d, const u32* a, u32 b0, u32 b1) {
    asm volatile("mma.sync.aligned.m16n8k16.row.col.f32.bf16.bf16.f32 "
                 "{%0,%1,%2,%3}, {%4,%5,%6,%7}, {%8,%9}, {%0,%1,%2,%3};"
                 : "+f"(d[0]), "+f"(d[1]), "+f"(d[2]), "+f"(d[3])
                 : "r"(a[0]), "r"(a[1]), "r"(a[2]), "r"(a[3]), "r"(b0), "r"(b1));
}

// ---- cp.async helpers ----
__device__ __forceinline__ void cpa16(u32 s, const void* g) {
    asm volatile("cp.async.cg.shared.global [%0], [%1], 16;" :: "r"(s), "l"(g) : "memory");
}
#define CP_COMMIT() asm volatile("cp.async.commit_group;" ::: "memory")
#define CP_WAIT(n)  asm volatile("cp.async.wait_group %0;" :: "n"(n) : "memory")

// ---------------------------------------------------------------------------
// Scratch (allocation-free rule: __device__ globals)
// ---------------------------------------------------------------------------
__device__ __nv_bfloat16 g_qh[AT_B * AT_T * AT_C], g_ql[AT_B * AT_T * AT_C];
__device__ __nv_bfloat16 g_kh[AT_B * AT_T * AT_C], g_kl[AT_B * AT_T * AT_C];
__device__ __nv_bfloat16 g_vh[AT_B * AT_T * AT_C], g_vl[AT_B * AT_T * AT_C];
__device__ __nv_bfloat16 g_wih[(AT_C + 2 * AT_KV) * AT_C], g_wil[(AT_C + 2 * AT_KV) * AT_C];
__device__ __nv_bfloat16 g_woh[AT_C * AT_C], g_wol[AT_C * AT_C];
__device__ __nv_bfloat16 g_xqh[AT_B * AT_T * AT_C],  g_xql[AT_B * AT_T * AT_C];
__device__ __nv_bfloat16 g_xkh[AT_B * AT_T * AT_KV], g_xkl[AT_B * AT_T * AT_KV];
__device__ __nv_bfloat16 g_xvh[AT_B * AT_T * AT_KV], g_xvl[AT_B * AT_T * AT_KV];
__device__ __nv_bfloat16 g_xoh[AT_B * AT_T * AT_C], g_xol[AT_B * AT_T * AT_C];

// ---------------------------------------------------------------------------
// fp32 -> (bf16 hi, bf16 lo) split
// ---------------------------------------------------------------------------
__global__ void split_kernel(const float4* __restrict__ src,
                             uint2* __restrict__ hi, uint2* __restrict__ lo, int n4)
{
    for (int i = blockIdx.x * blockDim.x + threadIdx.x; i < n4; i += gridDim.x * blockDim.x) {
        float4 v = src[i];
        u32 h0, l0, h1, l1;
        pack2hl(v.x, v.y, h0, l0);
        pack2hl(v.z, v.w, h1, l1);
        hi[i] = make_uint2(h0, h1);
        lo[i] = make_uint2(l0, l1);
    }
}

// ---------------------------------------------------------------------------
// bf16x3 HMMA GEMM with cp.async 4-stage pipeline.
// out[M,N] = (Ah+Al)[M,K] @ (Wh+Wl)[N,K]^T + bias[N]
// Block tile 128x128, BK=16, 256 threads, 8 warps of 64x32 warp tiles.
// Stage = [Ah 6K][Al 6K][Bh 6K][Bl 6K] = 24KB, 4 stages = 96KB dynamic smem.
// Rows pitch 48B (conflict-free for both cp.async stores and ldmatrix).
// Register discipline: one A-frag array reused across passes -> <=128 regs,
// 2 CTAs/SM.
// ---------------------------------------------------------------------------
#define STAGE_B 24576u

template<bool SPLIT>
__global__ __launch_bounds__(256, 2)
void gemm_mma(const __nv_bfloat16* __restrict__ Ahi, const __nv_bfloat16* __restrict__ Alo,
              const __nv_bfloat16* __restrict__ Whi, const __nv_bfloat16* __restrict__ Wlo,
              const float* __restrict__ bias, float* __restrict__ out,
              __nv_bfloat16* __restrict__ oh, __nv_bfloat16* __restrict__ ol,
              int N, int K)
{
    extern __shared__ __align__(16) char dsm[];
    const u32 sb  = (u32)__cvta_generic_to_shared(dsm);
    const int tid = threadIdx.x;

    const int m0 = blockIdx.y * 128;
    const int n0 = blockIdx.x * 128;

    // per-thread load slots: j = tid + t*256 over 512 16B-chunks per matrix
    // arr = j>>8 (hi/lo), row = (j>>1)&127, chunk = j&1
    auto load_stage = [&](int kt) {
        const u32 base = sb + (u32)(kt & 3) * STAGE_B;
        const int kofs = kt * 16;
        #pragma unroll
        for (int t = 0; t < 2; t++) {
            int j = tid + t * 256;
            int arr = j >> 8, r = (j >> 1) & 127, c = j & 1;
            const __nv_bfloat16* gp = (arr ? Alo : Ahi) + (size_t)(m0 + r) * K + kofs + c * 8;
            cpa16(base + arr * 6144 + r * 48 + c * 16, gp);
        }
        #pragma unroll
        for (int t = 0; t < 2; t++) {
            int j = tid + t * 256;
            int arr = j >> 8, r = (j >> 1) & 127, c = j & 1;
            const __nv_bfloat16* gp = (arr ? Wlo : Whi) + (size_t)(n0 + r) * K + kofs + c * 8;
            cpa16(base + 12288 + arr * 6144 + r * 48 + c * 16, gp);
        }
        CP_COMMIT();
    };

    load_stage(0);
    load_stage(1);
    load_stage(2);

    const int wid  = tid >> 5, lane = tid & 31;
    const int wm   = (wid & 1) << 6;     // warp m offset (0/64)
    const int wn   = (wid >> 1) << 5;    // warp n offset (0/32/64/96)

    const u32 a_off = (u32)((wm + (lane & 7) + ((lane >> 3) & 1) * 8) * 48 + (lane >> 4) * 16);
    const u32 b_off = (u32)((wn + (lane & 7) + (lane >> 4) * 8) * 48 + ((lane >> 3) & 1) * 16);

    float acc[4][4][4] = {};

    const int nk = K >> 4;
    for (int kt = 0; kt < nk; kt++) {
        if (kt + 3 < nk) { CP_WAIT(2); } else { CP_WAIT(0); }
        __syncthreads();

        const u32 base = sb + (u32)(kt & 3) * STAGE_B;
        u32 af[4][4], bh[2][4], bl[2][4];

        // pass 1: Al * Bh
        #pragma unroll
        for (int mf = 0; mf < 4; mf++) ldsm4(af[mf], base + 6144 + a_off + mf * 768);
        #pragma unroll
        for (int pf = 0; pf < 2; pf++) ldsm4(bh[pf], base + 12288 + b_off + pf * 768);
        #pragma unroll
        for (int mf = 0; mf < 4; mf++)
            #pragma unroll
            for (int nf = 0; nf < 4; nf++)
                mma_bf16(acc[mf][nf], af[mf], bh[nf >> 1][(nf & 1) * 2], bh[nf >> 1][(nf & 1) * 2 + 1]);

        // pass 2: Ah * Bh (reuse af for Ah)
        #pragma unroll
        for (int mf = 0; mf < 4; mf++) ldsm4(af[mf], base + a_off + mf * 768);
        #pragma unroll
        for (int mf = 0; mf < 4; mf++)
            #pragma unroll
            for (int nf = 0; nf < 4; nf++)
                mma_bf16(acc[mf][nf], af[mf], bh[nf >> 1][(nf & 1) * 2], bh[nf >> 1][(nf & 1) * 2 + 1]);

        // pass 3: Ah * Bl
        #pragma unroll
        for (int pf = 0; pf < 2; pf++) ldsm4(bl[pf], base + 18432 + b_off + pf * 768);
        #pragma unroll
        for (int mf = 0; mf < 4; mf++)
            #pragma unroll
            for (int nf = 0; nf < 4; nf++)
                mma_bf16(acc[mf][nf], af[mf], bl[nf >> 1][(nf & 1) * 2], bl[nf >> 1][(nf & 1) * 2 + 1]);

        if (kt + 3 < nk) load_stage(kt + 3);
    }

    // Epilogue (layout identical to R8/R9)
    const int gr  = lane >> 2;
    const int gc2 = (lane & 3) * 2;
    #pragma unroll
    for (int mf = 0; mf < 4; mf++) {
        int row0 = blockIdx.y * 128 + wm + mf * 16 + gr;
        #pragma unroll
        for (int nf = 0; nf < 4; nf++) {
            int col = blockIdx.x * 128 + wn + nf * 8 + gc2;
            float2 bv = *(const float2*)(bias + col);
            float v00 = acc[mf][nf][0] + bv.x, v01 = acc[mf][nf][1] + bv.y;
            float v10 = acc[mf][nf][2] + bv.x, v11 = acc[mf][nf][3] + bv.y;
            if (SPLIT) {
                u32 h0, l0, h1, l1;
                pack2hl(v00, v01, h0, l0);
                pack2hl(v10, v11, h1, l1);
                *(u32*)(oh + (size_t)row0 * N + col)       = h0;
                *(u32*)(ol + (size_t)row0 * N + col)       = l0;
                *(u32*)(oh + (size_t)(row0 + 8) * N + col) = h1;
                *(u32*)(ol + (size_t)(row0 + 8) * N + col) = l1;
            } else {
                *(float2*)(out + (size_t)row0 * N + col)       = make_float2(v00, v01);
                *(float2*)(out + (size_t)(row0 + 8) * N + col) = make_float2(v10, v11);
            }
        }
    }
}

// ---------------------------------------------------------------------------
// Tensor-core flash attention (causal, GQA), bf16x3 — unchanged from R9.
// ---------------------------------------------------------------------------
__global__ __launch_bounds__(256, 1)
void attn_tc_kernel()
{
    extern __shared__ __align__(16) __nv_bfloat16 smx[];
    __nv_bfloat16* Qh_s = smx;                 // [128][136]
    __nv_bfloat16* Ql_s = smx + 17408;
    __nv_bfloat16* Kh_s = smx + 34816;         // [64][136]
    __nv_bfloat16* Kl_s = smx + 43520;
    __nv_bfloat16* Vh_s = smx + 52224;         // [64][136]
    __nv_bfloat16* Vl_s = smx + 60928;
    const u32 sb  = (u32)__cvta_generic_to_shared(smx);
    const u32 QH = 0, QL = 34816, KH = 69632, KL = 87040, VH = 104448, VL = 121856;

    const int tid  = threadIdx.x;
    const int wid  = tid >> 5, lane = tid & 31;
    const int bh   = blockIdx.x;
    const int b    = bh >> 4;
    const int hd   = bh & 15;
    const int hkv  = hd & 3;
    const int qi   = 15 - blockIdx.y;          // heavy blocks first
    const int q0   = qi * 128;

    const __nv_bfloat16* qhp = g_xqh + ((size_t)b * AT_T + q0) * AT_C + hd * AT_D;
    const __nv_bfloat16* qlp = g_xql + ((size_t)b * AT_T + q0) * AT_C + hd * AT_D;
    const __nv_bfloat16* khp = g_xkh + (size_t)b * AT_T * AT_KV + hkv * AT_D;
    const __nv_bfloat16* klp = g_xkl + (size_t)b * AT_T * AT_KV + hkv * AT_D;
    const __nv_bfloat16* vhp = g_xvh + (size_t)b * AT_T * AT_KV + hkv * AT_D;
    const __nv_bfloat16* vlp = g_xvl + (size_t)b * AT_T * AT_KV + hkv * AT_D;

    for (int i = tid; i < 2048; i += 256) {
        int row = i >> 4, cc = (i & 15) << 3;
        *(uint4*)(Qh_s + row * 136 + cc) = *(const uint4*)(qhp + (size_t)row * AT_C + cc);
        *(uint4*)(Ql_s + row * 136 + cc) = *(const uint4*)(qlp + (size_t)row * AT_C + cc);
    }

    const int wq = wid * 16;
    const int gr = lane >> 2;
    const int qrow0 = q0 + wq + gr;
    const int qrow1 = qrow0 + 8;

    const u32 a_off = (u32)((wq + (lane & 7) + ((lane >> 3) & 1) * 8) * 272 + (lane >> 4) * 16);
    const u32 b_off = (u32)(((lane & 7) + (lane >> 4) * 8) * 272 + ((lane >> 3) & 1) * 16);
    const u32 v_off = (u32)(((lane & 7) + ((lane >> 3) & 1) * 8) * 272 + (lane >> 4) * 16);

    float o[16][4];
    #pragma unroll
    for (int nf = 0; nf < 16; nf++)
        #pragma unroll
        for (int k = 0; k < 4; k++) o[nf][k] = 0.f;
    float m0 = -1e30f, m1 = -1e30f, l0 = 0.f, l1 = 0.f;

    const int ntiles = 2 * qi + 2;
    for (int j = 0; j < ntiles; j++) {
        __syncthreads();
        for (int i = tid; i < 1024; i += 256) {
            int row = i >> 4, cc = (i & 15) << 3;
            size_t g = (size_t)(j * 64 + row) * AT_KV + cc;
            *(uint4*)(Kh_s + row * 136 + cc) = *(const uint4*)(khp + g);
            *(uint4*)(Kl_s + row * 136 + cc) = *(const uint4*)(klp + g);
            *(uint4*)(Vh_s + row * 136 + cc) = *(const uint4*)(vhp + g);
            *(uint4*)(Vl_s + row * 136 + cc) = *(const uint4*)(vlp + g);
        }
        __syncthreads();

        float s[8][4];
        #pragma unroll
        for (int nf = 0; nf < 8; nf++)
            #pragma unroll
            for (int k = 0; k < 4; k++) s[nf][k] = 0.f;

        #pragma unroll
        for (int c = 0; c < 8; c++) {
            u32 ah[4], al[4];
            ldsm4(ah, sb + QH + a_off + c * 32);
            ldsm4(al, sb + QL + a_off + c * 32);
            #pragma unroll
            for (int nb = 0; nb < 4; nb++) {
                u32 bh_[4], bl_[4];
                u32 ka = b_off + nb * 4352 + c * 32;
                ldsm4(bh_, sb + KH + ka);
                ldsm4(bl_, sb + KL + ka);
                mma_bf16(s[2 * nb],     al, bh_[0], bh_[1]);
                mma_bf16(s[2 * nb + 1], al, bh_[2], bh_[3]);
                mma_bf16(s[2 * nb],     ah, bl_[0], bl_[1]);
                mma_bf16(s[2 * nb + 1], ah, bl_[2], bl_[3]);
                mma_bf16(s[2 * nb],     ah, bh_[0], bh_[1]);
                mma_bf16(s[2 * nb + 1], ah, bh_[2], bh_[3]);
            }
        }

        const bool maskt = (j >= 2 * qi);
        const int colb = j * 64 + 2 * (lane & 3);
        float mx0 = -1e30f, mx1 = -1e30f;
        #pragma unroll
        for (int nf = 0; nf < 8; nf++) {
            int c0 = colb + 8 * nf;
            s[nf][0] *= AT_SCALE; s[nf][1] *= AT_SCALE;
            s[nf][2] *= AT_SCALE; s[nf][3] *= AT_SCALE;
            if (maskt) {
                if (c0     > qrow0) s[nf][0] = -1e30f;
                if (c0 + 1 > qrow0) s[nf][1] = -1e30f;
                if (c0     > qrow1) s[nf][2] = -1e30f;
                if (c0 + 1 > qrow1) s[nf][3] = -1e30f;
            }
            mx0 = fmaxf(mx0, fmaxf(s[nf][0], s[nf][1]));
            mx1 = fmaxf(mx1, fmaxf(s[nf][2], s[nf][3]));
        }
        mx0 = fmaxf(mx0, __shfl_xor_sync(0xffffffffu, mx0, 1));
        mx0 = fmaxf(mx0, __shfl_xor_sync(0xffffffffu, mx0, 2));
        mx1 = fmaxf(mx1, __shfl_xor_sync(0xffffffffu, mx1, 1));
        mx1 = fmaxf(mx1, __shfl_xor_sync(0xffffffffu, mx1, 2));

        float nm0 = fmaxf(m0, mx0), nm1 = fmaxf(m1, mx1);
        float corr0 = __expf(m0 - nm0), corr1 = __expf(m1 - nm1);
        m0 = nm0; m1 = nm1;

        float rs0 = 0.f, rs1 = 0.f;
        #pragma unroll
        for (int nf = 0; nf < 8; nf++) {
            s[nf][0] = __expf(s[nf][0] - m0); rs0 += s[nf][0];
            s[nf][1] = __expf(s[nf][1] - m0); rs0 += s[nf][1];
            s[nf][2] = __expf(s[nf][2] - m1); rs1 += s[nf][2];
            s[nf][3] = __expf(s[nf][3] - m1); rs1 += s[nf][3];
        }
        rs0 += __shfl_xor_sync(0xffffffffu, rs0, 1);
        rs0 += __shfl_xor_sync(0xffffffffu, rs0, 2);
        rs1 += __shfl_xor_sync(0xffffffffu, rs1, 1);
        rs1 += __shfl_xor_sync(0xffffffffu, rs1, 2);
        l0 = l0 * corr0 + rs0;
        l1 = l1 * corr1 + rs1;

        #pragma unroll
        for (int nf = 0; nf < 16; nf++) {
            o[nf][0] *= corr0; o[nf][1] *= corr0;
            o[nf][2] *= corr1; o[nf][3] *= corr1;
        }

        #pragma unroll
        for (int c = 0; c < 4; c++) {
            u32 aph[4], apl[4];
            pack2hl(s[2 * c][0],     s[2 * c][1],     aph[0], apl[0]);
            pack2hl(s[2 * c][2],     s[2 * c][3],     aph[1], apl[1]);
            pack2hl(s[2 * c + 1][0], s[2 * c + 1][1], aph[2], apl[2]);
            pack2hl(s[2 * c + 1][2], s[2 * c + 1][3], aph[3], apl[3]);
            #pragma unroll
            for (int nb = 0; nb < 8; nb++) {
                u32 vh_[4], vl_[4];
                u32 va = v_off + c * 4352 + nb * 32;
                ldsm4t(vh_, sb + VH + va);
                ldsm4t(vl_, sb + VL + va);
                mma_bf16(o[2 * nb],     aph, vh_[0], vh_[1]);
                mma_bf16(o[2 * nb + 1], aph, vh_[2], vh_[3]);
                mma_bf16(o[2 * nb],     aph, vl_[0], vl_[1]);
                mma_bf16(o[2 * nb + 1], aph, vl_[2], vl_[3]);
                mma_bf16(o[2 * nb],     apl, vh_[0], vh_[1]);
                mma_bf16(o[2 * nb + 1], apl, vh_[2], vh_[3]);
            }
        }
    }

    const float inv0 = 1.0f / l0, inv1 = 1.0f / l1;
    const size_t obase = (size_t)b * AT_T * AT_C + (size_t)hd * AT_D;
    #pragma unroll
    for (int nf = 0; nf < 16; nf++) {
        int d = nf * 8 + 2 * (lane & 3);
        u32 h0, lo0, h1, lo1;
        pack2hl(o[nf][0] * inv0, o[nf][1] * inv0, h0, lo0);
        pack2hl(o[nf][2] * inv1, o[nf][3] * inv1, h1, lo1);
        size_t i0 = obase + (size_t)qrow0 * AT_C + d;
        size_t i1 = obase + (size_t)qrow1 * AT_C + d;
        *(u32*)(g_xoh + i0) = h0;  *(u32*)(g_xol + i0) = lo0;
        *(u32*)(g_xoh + i1) = h1;  *(u32*)(g_xol + i1) = lo1;
    }
}

// ---------------------------------------------------------------------------
// Launch: split prep -> 3 projections -> TC attention -> out proj
// ---------------------------------------------------------------------------
extern "C" void kernel_launch(void* const* d_in, const int* in_sizes, int n_in,
                              void* d_out, int out_size)
{
    const float* q   = (const float*)d_in[0];
    const float* k   = (const float*)d_in[1];
    const float* v   = (const float*)d_in[2];
    const float* ipw = (const float*)d_in[3];  // (3072, 2048)
    const float* ipb = (const float*)d_in[4];  // (3072,)
    const float* opw = (const float*)d_in[5];  // (2048, 2048)
    const float* opb = (const float*)d_in[6];  // (2048,)
    float* out = (float*)d_out;

    __nv_bfloat16 *qh, *ql, *kh, *kl, *vh, *vl, *wih, *wil, *woh, *wol;
    __nv_bfloat16 *xqh, *xql, *xkh, *xkl, *xvh, *xvl, *xoh, *xol;
    cudaGetSymbolAddress((void**)&qh, g_qh);   cudaGetSymbolAddress((void**)&ql, g_ql);
    cudaGetSymbolAddress((void**)&kh, g_kh);   cudaGetSymbolAddress((void**)&kl, g_kl);
    cudaGetSymbolAddress((void**)&vh, g_vh);   cudaGetSymbolAddress((void**)&vl, g_vl);
    cudaGetSymbolAddress((void**)&wih, g_wih); cudaGetSymbolAddress((void**)&wil, g_wil);
    cudaGetSymbolAddress((void**)&woh, g_woh); cudaGetSymbolAddress((void**)&wol, g_wol);
    cudaGetSymbolAddress((void**)&xqh, g_xqh); cudaGetSymbolAddress((void**)&xql, g_xql);
    cudaGetSymbolAddress((void**)&xkh, g_xkh); cudaGetSymbolAddress((void**)&xkl, g_xkl);
    cudaGetSymbolAddress((void**)&xvh, g_xvh); cudaGetSymbolAddress((void**)&xvl, g_xvl);
    cudaGetSymbolAddress((void**)&xoh, g_xoh); cudaGetSymbolAddress((void**)&xol, g_xol);

    const int attn_smem = 139264;
    cudaFuncSetAttribute(attn_tc_kernel, cudaFuncAttributeMaxDynamicSharedMemorySize, attn_smem);
    const int gemm_smem = 4 * STAGE_B;  // 98304
    cudaFuncSetAttribute(gemm_mma<true>,  cudaFuncAttributeMaxDynamicSharedMemorySize, gemm_smem);
    cudaFuncSetAttribute(gemm_mma<false>, cudaFuncAttributeMaxDynamicSharedMemorySize, gemm_smem);

    dim3 blk(256);
    const int M_BLK = (AT_B * AT_T) / 128;  // 64

    // Prep: split inputs + weights into bf16 hi/lo
    const int n_act = AT_B * AT_T * AT_C / 4;
    const int n_ipw = (AT_C + 2 * AT_KV) * AT_C / 4;
    const int n_opw = AT_C * AT_C / 4;
    split_kernel<<<4096, 256>>>((const float4*)q,   (uint2*)qh,  (uint2*)ql,  n_act);
    split_kernel<<<4096, 256>>>((const float4*)k,   (uint2*)kh,  (uint2*)kl,  n_act);
    split_kernel<<<4096, 256>>>((const float4*)v,   (uint2*)vh,  (uint2*)vl,  n_act);
    split_kernel<<<4096, 256>>>((const float4*)ipw, (uint2*)wih, (uint2*)wil, n_ipw);
    split_kernel<<<4096, 256>>>((const float4*)opw, (uint2*)woh, (uint2*)wol, n_opw);

    // Projections: bf16x3 HMMA GEMMs with cp.async pipeline
    gemm_mma<true><<<dim3(AT_C / 128, M_BLK), blk, gemm_smem>>>(
        qh, ql, wih, wil, ipb, nullptr, xqh, xql, AT_C, AT_C);
    gemm_mma<true><<<dim3(AT_KV / 128, M_BLK), blk, gemm_smem>>>(
        kh, kl, wih + (size_t)AT_C * AT_C, wil + (size_t)AT_C * AT_C,
        ipb + AT_C, nullptr, xkh, xkl, AT_KV, AT_C);
    gemm_mma<true><<<dim3(AT_KV / 128, M_BLK), blk, gemm_smem>>>(
        vh, vl, wih + (size_t)(AT_C + AT_KV) * AT_C, wil + (size_t)(AT_C + AT_KV) * AT_C,
        ipb + AT_C + AT_KV, nullptr, xvh, xvl, AT_KV, AT_C);

    // Tensor-core causal GQA flash attention
    attn_tc_kernel<<<dim3(AT_B * AT_H, AT_T / 128), blk, attn_smem>>>();

    // Output projection (fp32 out)
    gemm_mma<false><<<dim3(AT_C / 128, M_BLK), blk, gemm_smem>>>(
        xoh, xol, woh, wol, opb, out, nullptr, nullptr, AT_C, AT_C);
}

// round 12
// speedup vs baseline: 2.7244x; 1.0687x over previous
#include <cuda_runtime.h>
#include <cuda_bf16.h>
#include <cstdint>
#include <cstddef>

// Problem constants: B=4, T=2048, C=2048, H=16, G=4, HKV=4, D=128, KV=512
#define AT_B   4
#define AT_T   2048
#define AT_C   2048
#define AT_KV  512
#define AT_D   128
#define AT_H   16
#define AT_HKV 4
#define AT_SCALE 0.08838834764831845f  // 1/sqrt(128)

typedef unsigned long long u64;
typedef unsigned int u32;

// ---------------------------------------------------------------------------
// Common helpers
// ---------------------------------------------------------------------------
__device__ __forceinline__ void pack2hl(float x, float y, u32& h, u32& l) {
    __nv_bfloat162 hv = __float22bfloat162_rn(make_float2(x, y));
    float lx = x - __low2float(hv), ly = y - __high2float(hv);
    __nv_bfloat162 lv = __float22bfloat162_rn(make_float2(lx, ly));
    h = *reinterpret_cast<u32*>(&hv);
    l = *reinterpret_cast<u32*>(&lv);
}

// ---- legacy mma helpers (proven in R8/R9/R11) ----
__device__ __forceinline__ void ldsm4(u32* r, u32 addr) {
    asm volatile("ldmatrix.sync.aligned.m8n8.x4.shared.b16 {%0,%1,%2,%3}, [%4];"
                 : "=r"(r[0]), "=r"(r[1]), "=r"(r[2]), "=r"(r[3]) : "r"(addr));
}
__device__ __forceinline__ void ldsm4t(u32* r, u32 addr) {
    asm volatile("ldmatrix.sync.aligned.m8n8.x4.trans.shared.b16 {%0,%1,%2,%3}, [%4];"
                 : "=r"(r[0]), "=r"(r[1]), "=r"(r[2]), "=r"(r[3]) : "r"(addr));
}
__device__ __forceinline__ void mma_bf16(float* d, const u32* a, u32 b0, u32 b1) {
    asm volatile("mma.sync.aligned.m16n8k16.row.col.f32.bf16.bf16.f32 "
                 "{%0,%1,%2,%3}, {%4,%5,%6,%7}, {%8,%9}, {%0,%1,%2,%3};"
                 : "+f"(d[0]), "+f"(d[1]), "+f"(d[2]), "+f"(d[3])
                 : "r"(a[0]), "r"(a[1]), "r"(a[2]), "r"(a[3]), "r"(b0), "r"(b1));
}

// ---- cp.async helpers ----
__device__ __forceinline__ void cpa16(u32 s, const void* g) {
    asm volatile("cp.async.cg.shared.global [%0], [%1], 16;" :: "r"(s), "l"(g) : "memory");
}
#define CP_COMMIT() asm volatile("cp.async.commit_group;" ::: "memory")
#define CP_WAIT(n)  asm volatile("cp.async.wait_group %0;" :: "n"(n) : "memory")

// ---------------------------------------------------------------------------
// Scratch (allocation-free rule: __device__ globals)
// ---------------------------------------------------------------------------
__device__ __nv_bfloat16 g_qh[AT_B * AT_T * AT_C], g_ql[AT_B * AT_T * AT_C];
__device__ __nv_bfloat16 g_kh[AT_B * AT_T * AT_C], g_kl[AT_B * AT_T * AT_C];
__device__ __nv_bfloat16 g_vh[AT_B * AT_T * AT_C], g_vl[AT_B * AT_T * AT_C];
__device__ __nv_bfloat16 g_wih[(AT_C + 2 * AT_KV) * AT_C], g_wil[(AT_C + 2 * AT_KV) * AT_C];
__device__ __nv_bfloat16 g_woh[AT_C * AT_C], g_wol[AT_C * AT_C];
__device__ __nv_bfloat16 g_xqh[AT_B * AT_T * AT_C],  g_xql[AT_B * AT_T * AT_C];
__device__ __nv_bfloat16 g_xkh[AT_B * AT_T * AT_KV], g_xkl[AT_B * AT_T * AT_KV];
__device__ __nv_bfloat16 g_xvh[AT_B * AT_T * AT_KV], g_xvl[AT_B * AT_T * AT_KV];
__device__ __nv_bfloat16 g_xoh[AT_B * AT_T * AT_C], g_xol[AT_B * AT_T * AT_C];

// ---------------------------------------------------------------------------
// Fused fp32 -> (bf16 hi, bf16 lo) split over all 5 tensors (one launch)
// ---------------------------------------------------------------------------
#define N_ACT (AT_B * AT_T * AT_C / 4)             // 2097152 float4
#define N_IPW ((AT_C + 2 * AT_KV) * AT_C / 4)      // 1572864
#define N_OPW (AT_C * AT_C / 4)                    // 1048576

__global__ void split_all_kernel(const float4* __restrict__ q, const float4* __restrict__ k,
                                 const float4* __restrict__ v, const float4* __restrict__ ipw,
                                 const float4* __restrict__ opw,
                                 uint2* qh, uint2* ql, uint2* kh, uint2* kl,
                                 uint2* vh, uint2* vl, uint2* wih, uint2* wil,
                                 uint2* woh, uint2* wol)
{
    const int total = 3 * N_ACT + N_IPW + N_OPW;
    for (int i = blockIdx.x * blockDim.x + threadIdx.x; i < total; i += gridDim.x * blockDim.x) {
        const float4* src; uint2 *hi, *lo; int j = i;
        if (j < N_ACT)                    { src = q;   hi = qh;  lo = ql;  }
        else if ((j -= N_ACT) < N_ACT)    { src = k;   hi = kh;  lo = kl;  }
        else if ((j -= N_ACT) < N_ACT)    { src = v;   hi = vh;  lo = vl;  }
        else if ((j -= N_ACT) < N_IPW)    { src = ipw; hi = wih; lo = wil; }
        else { j -= N_IPW;                  src = opw; hi = woh; lo = wol; }
        float4 val = src[j];
        u32 h0, l0, h1, l1;
        pack2hl(val.x, val.y, h0, l0);
        pack2hl(val.z, val.w, h1, l1);
        hi[j] = make_uint2(h0, h1);
        lo[j] = make_uint2(l0, l1);
    }
}

// ---------------------------------------------------------------------------
// bf16x3 HMMA GEMM with cp.async 4-stage pipeline (unchanged from R11).
// ---------------------------------------------------------------------------
#define STAGE_B 24576u

template<bool SPLIT>
__global__ __launch_bounds__(256, 2)
void gemm_mma(const __nv_bfloat16* __restrict__ Ahi, const __nv_bfloat16* __restrict__ Alo,
              const __nv_bfloat16* __restrict__ Whi, const __nv_bfloat16* __restrict__ Wlo,
              const float* __restrict__ bias, float* __restrict__ out,
              __nv_bfloat16* __restrict__ oh, __nv_bfloat16* __restrict__ ol,
              int N, int K)
{
    extern __shared__ __align__(16) char dsm[];
    const u32 sb  = (u32)__cvta_generic_to_shared(dsm);
    const int tid = threadIdx.x;

    const int m0 = blockIdx.y * 128;
    const int n0 = blockIdx.x * 128;

    auto load_stage = [&](int kt) {
        const u32 base = sb + (u32)(kt & 3) * STAGE_B;
        const int kofs = kt * 16;
        #pragma unroll
        for (int t = 0; t < 2; t++) {
            int j = tid + t * 256;
            int arr = j >> 8, r = (j >> 1) & 127, c = j & 1;
            const __nv_bfloat16* gp = (arr ? Alo : Ahi) + (size_t)(m0 + r) * K + kofs + c * 8;
            cpa16(base + arr * 6144 + r * 48 + c * 16, gp);
        }
        #pragma unroll
        for (int t = 0; t < 2; t++) {
            int j = tid + t * 256;
            int arr = j >> 8, r = (j >> 1) & 127, c = j & 1;
            const __nv_bfloat16* gp = (arr ? Wlo : Whi) + (size_t)(n0 + r) * K + kofs + c * 8;
            cpa16(base + 12288 + arr * 6144 + r * 48 + c * 16, gp);
        }
        CP_COMMIT();
    };

    load_stage(0);
    load_stage(1);
    load_stage(2);

    const int wid  = tid >> 5, lane = tid & 31;
    const int wm   = (wid & 1) << 6;
    const int wn   = (wid >> 1) << 5;

    const u32 a_off = (u32)((wm + (lane & 7) + ((lane >> 3) & 1) * 8) * 48 + (lane >> 4) * 16);
    const u32 b_off = (u32)((wn + (lane & 7) + (lane >> 4) * 8) * 48 + ((lane >> 3) & 1) * 16);

    float acc[4][4][4] = {};

    const int nk = K >> 4;
    for (int kt = 0; kt < nk; kt++) {
        if (kt + 3 < nk) { CP_WAIT(2); } else { CP_WAIT(0); }
        __syncthreads();

        const u32 base = sb + (u32)(kt & 3) * STAGE_B;
        u32 af[4][4], bh[2][4], bl[2][4];

        #pragma unroll
        for (int mf = 0; mf < 4; mf++) ldsm4(af[mf], base + 6144 + a_off + mf * 768);
        #pragma unroll
        for (int pf = 0; pf < 2; pf++) ldsm4(bh[pf], base + 12288 + b_off + pf * 768);
        #pragma unroll
        for (int mf = 0; mf < 4; mf++)
            #pragma unroll
            for (int nf = 0; nf < 4; nf++)
                mma_bf16(acc[mf][nf], af[mf], bh[nf >> 1][(nf & 1) * 2], bh[nf >> 1][(nf & 1) * 2 + 1]);

        #pragma unroll
        for (int mf = 0; mf < 4; mf++) ldsm4(af[mf], base + a_off + mf * 768);
        #pragma unroll
        for (int mf = 0; mf < 4; mf++)
            #pragma unroll
            for (int nf = 0; nf < 4; nf++)
                mma_bf16(acc[mf][nf], af[mf], bh[nf >> 1][(nf & 1) * 2], bh[nf >> 1][(nf & 1) * 2 + 1]);

        #pragma unroll
        for (int pf = 0; pf < 2; pf++) ldsm4(bl[pf], base + 18432 + b_off + pf * 768);
        #pragma unroll
        for (int mf = 0; mf < 4; mf++)
            #pragma unroll
            for (int nf = 0; nf < 4; nf++)
                mma_bf16(acc[mf][nf], af[mf], bl[nf >> 1][(nf & 1) * 2], bl[nf >> 1][(nf & 1) * 2 + 1]);

        if (kt + 3 < nk) load_stage(kt + 3);
    }

    const int gr  = lane >> 2;
    const int gc2 = (lane & 3) * 2;
    #pragma unroll
    for (int mf = 0; mf < 4; mf++) {
        int row0 = blockIdx.y * 128 + wm + mf * 16 + gr;
        #pragma unroll
        for (int nf = 0; nf < 4; nf++) {
            int col = blockIdx.x * 128 + wn + nf * 8 + gc2;
            float2 bv = *(const float2*)(bias + col);
            float v00 = acc[mf][nf][0] + bv.x, v01 = acc[mf][nf][1] + bv.y;
            float v10 = acc[mf][nf][2] + bv.x, v11 = acc[mf][nf][3] + bv.y;
            if (SPLIT) {
                u32 h0, l0, h1, l1;
                pack2hl(v00, v01, h0, l0);
                pack2hl(v10, v11, h1, l1);
                *(u32*)(oh + (size_t)row0 * N + col)       = h0;
                *(u32*)(ol + (size_t)row0 * N + col)       = l0;
                *(u32*)(oh + (size_t)(row0 + 8) * N + col) = h1;
                *(u32*)(ol + (size_t)(row0 + 8) * N + col) = l1;
            } else {
                *(float2*)(out + (size_t)row0 * N + col)       = make_float2(v00, v01);
                *(float2*)(out + (size_t)(row0 + 8) * N + col) = make_float2(v10, v11);
            }
        }
    }
}

// ---------------------------------------------------------------------------
// Tensor-core flash attention (causal, GQA), bf16x3.
// R12: BM=64, 128-thread CTAs (4 warps x 16 rows), smem 104448 B -> 2 CTAs/SM.
// Per-warp fragment maps identical to the proven R9 kernel.
// ---------------------------------------------------------------------------
__global__ __launch_bounds__(128, 2)
void attn_tc_kernel()
{
    extern __shared__ __align__(16) __nv_bfloat16 smx[];
    const u32 sb = (u32)__cvta_generic_to_shared(smx);
    // byte offsets; row pitch 136 halves = 272 B (conflict-free ldmatrix)
    const u32 QH = 0, QL = 17408, KH = 34816, KL = 52224, VH = 69632, VL = 87040;

    const int tid  = threadIdx.x;
    const int wid  = tid >> 5, lane = tid & 31;
    const int bx   = blockIdx.x;
    const int b    = bx >> 4;
    const int hd   = bx & 15;
    const int hkv  = hd & 3;
    const int qb   = 31 - blockIdx.y;          // heavy blocks first
    const int q0   = qb * 64;

    const __nv_bfloat16* qhp = g_xqh + ((size_t)b * AT_T + q0) * AT_C + hd * AT_D;
    const __nv_bfloat16* qlp = g_xql + ((size_t)b * AT_T + q0) * AT_C + hd * AT_D;
    const __nv_bfloat16* khp = g_xkh + (size_t)b * AT_T * AT_KV + hkv * AT_D;
    const __nv_bfloat16* klp = g_xkl + (size_t)b * AT_T * AT_KV + hkv * AT_D;
    const __nv_bfloat16* vhp = g_xvh + (size_t)b * AT_T * AT_KV + hkv * AT_D;
    const __nv_bfloat16* vlp = g_xvl + (size_t)b * AT_T * AT_KV + hkv * AT_D;

    // Q tile (64 x 128 halves, hi+lo) via cp.async
    for (int i = tid; i < 1024; i += 128) {
        int row = i >> 4, cc = (i & 15) << 3;
        size_t g = (size_t)row * AT_C + cc;
        cpa16(sb + QH + row * 272 + cc * 2, qhp + g);
        cpa16(sb + QL + row * 272 + cc * 2, qlp + g);
    }
    CP_COMMIT();

    const int wq = wid * 16;
    const int gr = lane >> 2;
    const int qrow0 = q0 + wq + gr;
    const int qrow1 = qrow0 + 8;

    const u32 a_off = (u32)((wq + (lane & 7) + ((lane >> 3) & 1) * 8) * 272 + (lane >> 4) * 16);
    const u32 b_off = (u32)(((lane & 7) + (lane >> 4) * 8) * 272 + ((lane >> 3) & 1) * 16);
    const u32 v_off = (u32)(((lane & 7) + ((lane >> 3) & 1) * 8) * 272 + (lane >> 4) * 16);

    float o[16][4];
    #pragma unroll
    for (int nf = 0; nf < 16; nf++)
        #pragma unroll
        for (int k = 0; k < 4; k++) o[nf][k] = 0.f;
    float m0 = -1e30f, m1 = -1e30f, l0 = 0.f, l1 = 0.f;

    for (int j = 0; j <= qb; j++) {
        if (j > 0) __syncthreads();            // previous K/V fully consumed
        for (int i = tid; i < 1024; i += 128) {
            int row = i >> 4, cc = (i & 15) << 3;
            size_t g = (size_t)(j * 64 + row) * AT_KV + cc;
            u32 so = row * 272 + cc * 2;
            cpa16(sb + KH + so, khp + g);
            cpa16(sb + KL + so, klp + g);
            cpa16(sb + VH + so, vhp + g);
            cpa16(sb + VL + so, vlp + g);
        }
        CP_COMMIT();
        CP_WAIT(0);
        __syncthreads();

        // ---- S = Q K^T (bf16x3) ----
        float s[8][4];
        #pragma unroll
        for (int nf = 0; nf < 8; nf++)
            #pragma unroll
            for (int k = 0; k < 4; k++) s[nf][k] = 0.f;

        #pragma unroll
        for (int c = 0; c < 8; c++) {
            u32 ah[4], al[4];
            ldsm4(ah, sb + QH + a_off + c * 32);
            ldsm4(al, sb + QL + a_off + c * 32);
            #pragma unroll
            for (int nb = 0; nb < 4; nb++) {
                u32 bh_[4], bl_[4];
                u32 ka = b_off + nb * 4352 + c * 32;
                ldsm4(bh_, sb + KH + ka);
                ldsm4(bl_, sb + KL + ka);
                mma_bf16(s[2 * nb],     al, bh_[0], bh_[1]);
                mma_bf16(s[2 * nb + 1], al, bh_[2], bh_[3]);
                mma_bf16(s[2 * nb],     ah, bl_[0], bl_[1]);
                mma_bf16(s[2 * nb + 1], ah, bl_[2], bl_[3]);
                mma_bf16(s[2 * nb],     ah, bh_[0], bh_[1]);
                mma_bf16(s[2 * nb + 1], ah, bh_[2], bh_[3]);
            }
        }

        // ---- online softmax ----
        const bool maskt = (j == qb);
        const int colb = j * 64 + 2 * (lane & 3);
        float mx0 = -1e30f, mx1 = -1e30f;
        #pragma unroll
        for (int nf = 0; nf < 8; nf++) {
            int c0 = colb + 8 * nf;
            s[nf][0] *= AT_SCALE; s[nf][1] *= AT_SCALE;
            s[nf][2] *= AT_SCALE; s[nf][3] *= AT_SCALE;
            if (maskt) {
                if (c0     > qrow0) s[nf][0] = -1e30f;
                if (c0 + 1 > qrow0) s[nf][1] = -1e30f;
                if (c0     > qrow1) s[nf][2] = -1e30f;
                if (c0 + 1 > qrow1) s[nf][3] = -1e30f;
            }
            mx0 = fmaxf(mx0, fmaxf(s[nf][0], s[nf][1]));
            mx1 = fmaxf(mx1, fmaxf(s[nf][2], s[nf][3]));
        }
        mx0 = fmaxf(mx0, __shfl_xor_sync(0xffffffffu, mx0, 1));
        mx0 = fmaxf(mx0, __shfl_xor_sync(0xffffffffu, mx0, 2));
        mx1 = fmaxf(mx1, __shfl_xor_sync(0xffffffffu, mx1, 1));
        mx1 = fmaxf(mx1, __shfl_xor_sync(0xffffffffu, mx1, 2));

        float nm0 = fmaxf(m0, mx0), nm1 = fmaxf(m1, mx1);
        float corr0 = __expf(m0 - nm0), corr1 = __expf(m1 - nm1);
        m0 = nm0; m1 = nm1;

        float rs0 = 0.f, rs1 = 0.f;
        #pragma unroll
        for (int nf = 0; nf < 8; nf++) {
            s[nf][0] = __expf(s[nf][0] - m0); rs0 += s[nf][0];
            s[nf][1] = __expf(s[nf][1] - m0); rs0 += s[nf][1];
            s[nf][2] = __expf(s[nf][2] - m1); rs1 += s[nf][2];
            s[nf][3] = __expf(s[nf][3] - m1); rs1 += s[nf][3];
        }
        rs0 += __shfl_xor_sync(0xffffffffu, rs0, 1);
        rs0 += __shfl_xor_sync(0xffffffffu, rs0, 2);
        rs1 += __shfl_xor_sync(0xffffffffu, rs1, 1);
        rs1 += __shfl_xor_sync(0xffffffffu, rs1, 2);
        l0 = l0 * corr0 + rs0;
        l1 = l1 * corr1 + rs1;

        #pragma unroll
        for (int nf = 0; nf < 16; nf++) {
            o[nf][0] *= corr0; o[nf][1] *= corr0;
            o[nf][2] *= corr1; o[nf][3] *= corr1;
        }

        // ---- O += P V (bf16x3) ----
        #pragma unroll
        for (int c = 0; c < 4; c++) {
            u32 aph[4], apl[4];
            pack2hl(s[2 * c][0],     s[2 * c][1],     aph[0], apl[0]);
            pack2hl(s[2 * c][2],     s[2 * c][3],     aph[1], apl[1]);
            pack2hl(s[2 * c + 1][0], s[2 * c + 1][1], aph[2], apl[2]);
            pack2hl(s[2 * c + 1][2], s[2 * c + 1][3], aph[3], apl[3]);
            #pragma unroll
            for (int nb = 0; nb < 8; nb++) {
                u32 vh_[4], vl_[4];
                u32 va = v_off + c * 4352 + nb * 32;
                ldsm4t(vh_, sb + VH + va);
                ldsm4t(vl_, sb + VL + va);
                mma_bf16(o[2 * nb],     aph, vh_[0], vh_[1]);
                mma_bf16(o[2 * nb + 1], aph, vh_[2], vh_[3]);
                mma_bf16(o[2 * nb],     aph, vl_[0], vl_[1]);
                mma_bf16(o[2 * nb + 1], aph, vl_[2], vl_[3]);
                mma_bf16(o[2 * nb],     apl, vh_[0], vh_[1]);
                mma_bf16(o[2 * nb + 1], apl, vh_[2], vh_[3]);
            }
        }
    }

    // ---- epilogue: O/l -> bf16 hi/lo ----
    const float inv0 = 1.0f / l0, inv1 = 1.0f / l1;
    const size_t obase = (size_t)b * AT_T * AT_C + (size_t)hd * AT_D;
    #pragma unroll
    for (int nf = 0; nf < 16; nf++) {
        int d = nf * 8 + 2 * (lane & 3);
        u32 h0, lo0, h1, lo1;
        pack2hl(o[nf][0] * inv0, o[nf][1] * inv0, h0, lo0);
        pack2hl(o[nf][2] * inv1, o[nf][3] * inv1, h1, lo1);
        size_t i0 = obase + (size_t)qrow0 * AT_C + d;
        size_t i1 = obase + (size_t)qrow1 * AT_C + d;
        *(u32*)(g_xoh + i0) = h0;  *(u32*)(g_xol + i0) = lo0;
        *(u32*)(g_xoh + i1) = h1;  *(u32*)(g_xol + i1) = lo1;
    }
}

// ---------------------------------------------------------------------------
// Launch: fused split -> 3 projections -> TC attention -> out proj
// ---------------------------------------------------------------------------
extern "C" void kernel_launch(void* const* d_in, const int* in_sizes, int n_in,
                              void* d_out, int out_size)
{
    const float* q   = (const float*)d_in[0];
    const float* k   = (const float*)d_in[1];
    const float* v   = (const float*)d_in[2];
    const float* ipw = (const float*)d_in[3];  // (3072, 2048)
    const float* ipb = (const float*)d_in[4];  // (3072,)
    const float* opw = (const float*)d_in[5];  // (2048, 2048)
    const float* opb = (const float*)d_in[6];  // (2048,)
    float* out = (float*)d_out;

    __nv_bfloat16 *qh, *ql, *kh, *kl, *vh, *vl, *wih, *wil, *woh, *wol;
    __nv_bfloat16 *xqh, *xql, *xkh, *xkl, *xvh, *xvl, *xoh, *xol;
    cudaGetSymbolAddress((void**)&qh, g_qh);   cudaGetSymbolAddress((void**)&ql, g_ql);
    cudaGetSymbolAddress((void**)&kh, g_kh);   cudaGetSymbolAddress((void**)&kl, g_kl);
    cudaGetSymbolAddress((void**)&vh, g_vh);   cudaGetSymbolAddress((void**)&vl, g_vl);
    cudaGetSymbolAddress((void**)&wih, g_wih); cudaGetSymbolAddress((void**)&wil, g_wil);
    cudaGetSymbolAddress((void**)&woh, g_woh); cudaGetSymbolAddress((void**)&wol, g_wol);
    cudaGetSymbolAddress((void**)&xqh, g_xqh); cudaGetSymbolAddress((void**)&xql, g_xql);
    cudaGetSymbolAddress((void**)&xkh, g_xkh); cudaGetSymbolAddress((void**)&xkl, g_xkl);
    cudaGetSymbolAddress((void**)&xvh, g_xvh); cudaGetSymbolAddress((void**)&xvl, g_xvl);
    cudaGetSymbolAddress((void**)&xoh, g_xoh); cudaGetSymbolAddress((void**)&xol, g_xol);

    const int attn_smem = 104448;  // (64+64+64) rows x 272 B x hi/lo
    cudaFuncSetAttribute(attn_tc_kernel, cudaFuncAttributeMaxDynamicSharedMemorySize, attn_smem);
    const int gemm_smem = 4 * STAGE_B;  // 98304
    cudaFuncSetAttribute(gemm_mma<true>,  cudaFuncAttributeMaxDynamicSharedMemorySize, gemm_smem);
    cudaFuncSetAttribute(gemm_mma<false>, cudaFuncAttributeMaxDynamicSharedMemorySize, gemm_smem);

    dim3 blk(256);
    const int M_BLK = (AT_B * AT_T) / 128;  // 64

    // Fused prep: split inputs + weights into bf16 hi/lo (one launch)
    split_all_kernel<<<4096, 256>>>((const float4*)q, (const float4*)k, (const float4*)v,
                                    (const float4*)ipw, (const float4*)opw,
                                    (uint2*)qh, (uint2*)ql, (uint2*)kh, (uint2*)kl,
                                    (uint2*)vh, (uint2*)vl, (uint2*)wih, (uint2*)wil,
                                    (uint2*)woh, (uint2*)wol);

    // Projections: bf16x3 HMMA GEMMs with cp.async pipeline
    gemm_mma<true><<<dim3(AT_C / 128, M_BLK), blk, gemm_smem>>>(
        qh, ql, wih, wil, ipb, nullptr, xqh, xql, AT_C, AT_C);
    gemm_mma<true><<<dim3(AT_KV / 128, M_BLK), blk, gemm_smem>>>(
        kh, kl, wih + (size_t)AT_C * AT_C, wil + (size_t)AT_C * AT_C,
        ipb + AT_C, nullptr, xkh, xkl, AT_KV, AT_C);
    gemm_mma<true><<<dim3(AT_KV / 128, M_BLK), blk, gemm_smem>>>(
        vh, vl, wih + (size_t)(AT_C + AT_KV) * AT_C, wil + (size_t)(AT_C + AT_KV) * AT_C,
        ipb + AT_C + AT_KV, nullptr, xvh, xvl, AT_KV, AT_C);

    // Tensor-core causal GQA flash attention (BM=64, occupancy 2)
    attn_tc_kernel<<<dim3(AT_B * AT_H, AT_T / 64), dim3(128), attn_smem>>>();

    // Output projection (fp32 out)
    gemm_mma<false><<<dim3(AT_C / 128, M_BLK), blk, gemm_smem>>>(
        xoh, xol, woh, wol, opb, out, nullptr, nullptr, AT_C, AT_C);
}

// round 13
// speedup vs baseline: 2.7365x; 1.0044x over previous
#include <cuda_runtime.h>
#include <cuda_bf16.h>
#include <cstdint>
#include <cstddef>

// Problem constants: B=4, T=2048, C=2048, H=16, G=4, HKV=4, D=128, KV=512
#define AT_B   4
#define AT_T   2048
#define AT_C   2048
#define AT_KV  512
#define AT_D   128
#define AT_H   16
#define AT_HKV 4
#define AT_SCALE 0.08838834764831845f  // 1/sqrt(128)

typedef unsigned long long u64;
typedef unsigned int u32;

// ---------------------------------------------------------------------------
// Common helpers
// ---------------------------------------------------------------------------
__device__ __forceinline__ void pack2hl(float x, float y, u32& h, u32& l) {
    __nv_bfloat162 hv = __float22bfloat162_rn(make_float2(x, y));
    float lx = x - __low2float(hv), ly = y - __high2float(hv);
    __nv_bfloat162 lv = __float22bfloat162_rn(make_float2(lx, ly));
    h = *reinterpret_cast<u32*>(&hv);
    l = *reinterpret_cast<u32*>(&lv);
}

// ---- legacy mma helpers (proven R8-R12) ----
__device__ __forceinline__ void ldsm4(u32* r, u32 addr) {
    asm volatile("ldmatrix.sync.aligned.m8n8.x4.shared.b16 {%0,%1,%2,%3}, [%4];"
                 : "=r"(r[0]), "=r"(r[1]), "=r"(r[2]), "=r"(r[3]) : "r"(addr));
}
__device__ __forceinline__ void ldsm4t(u32* r, u32 addr) {
    asm volatile("ldmatrix.sync.aligned.m8n8.x4.trans.shared.b16 {%0,%1,%2,%3}, [%4];"
                 : "=r"(r[0]), "=r"(r[1]), "=r"(r[2]), "=r"(r[3]) : "r"(addr));
}
__device__ __forceinline__ void mma_bf16(float* d, const u32* a, u32 b0, u32 b1) {
    asm volatile("mma.sync.aligned.m16n8k16.row.col.f32.bf16.bf16.f32 "
                 "{%0,%1,%2,%3}, {%4,%5,%6,%7}, {%8,%9}, {%0,%1,%2,%3};"
                 : "+f"(d[0]), "+f"(d[1]), "+f"(d[2]), "+f"(d[3])
                 : "r"(a[0]), "r"(a[1]), "r"(a[2]), "r"(a[3]), "r"(b0), "r"(b1));
}

// ---- cp.async helpers ----
__device__ __forceinline__ void cpa16(u32 s, const void* g) {
    asm volatile("cp.async.cg.shared.global [%0], [%1], 16;" :: "r"(s), "l"(g) : "memory");
}
#define CP_COMMIT() asm volatile("cp.async.commit_group;" ::: "memory")
#define CP_WAIT(n)  asm volatile("cp.async.wait_group %0;" :: "n"(n) : "memory")

// ---------------------------------------------------------------------------
// Scratch (allocation-free rule: __device__ globals)
// ---------------------------------------------------------------------------
__device__ __nv_bfloat16 g_qh[AT_B * AT_T * AT_C], g_ql[AT_B * AT_T * AT_C];
__device__ __nv_bfloat16 g_kh[AT_B * AT_T * AT_C], g_kl[AT_B * AT_T * AT_C];
__device__ __nv_bfloat16 g_vh[AT_B * AT_T * AT_C], g_vl[AT_B * AT_T * AT_C];
__device__ __nv_bfloat16 g_wih[(AT_C + 2 * AT_KV) * AT_C], g_wil[(AT_C + 2 * AT_KV) * AT_C];
__device__ __nv_bfloat16 g_woh[AT_C * AT_C], g_wol[AT_C * AT_C];
__device__ __nv_bfloat16 g_xqh[AT_B * AT_T * AT_C],  g_xql[AT_B * AT_T * AT_C];
__device__ __nv_bfloat16 g_xkh[AT_B * AT_T * AT_KV], g_xkl[AT_B * AT_T * AT_KV];
__device__ __nv_bfloat16 g_xvh[AT_B * AT_T * AT_KV], g_xvl[AT_B * AT_T * AT_KV];
__device__ __nv_bfloat16 g_xoh[AT_B * AT_T * AT_C], g_xol[AT_B * AT_T * AT_C];

// ---------------------------------------------------------------------------
// Fused fp32 -> (bf16 hi, bf16 lo) split over all 5 tensors (one launch)
// ---------------------------------------------------------------------------
#define N_ACT (AT_B * AT_T * AT_C / 4)
#define N_IPW ((AT_C + 2 * AT_KV) * AT_C / 4)
#define N_OPW (AT_C * AT_C / 4)

__global__ void split_all_kernel(const float4* __restrict__ q, const float4* __restrict__ k,
                                 const float4* __restrict__ v, const float4* __restrict__ ipw,
                                 const float4* __restrict__ opw,
                                 uint2* qh, uint2* ql, uint2* kh, uint2* kl,
                                 uint2* vh, uint2* vl, uint2* wih, uint2* wil,
                                 uint2* woh, uint2* wol)
{
    const int total = 3 * N_ACT + N_IPW + N_OPW;
    for (int i = blockIdx.x * blockDim.x + threadIdx.x; i < total; i += gridDim.x * blockDim.x) {
        const float4* src; uint2 *hi, *lo; int j = i;
        if (j < N_ACT)                    { src = q;   hi = qh;  lo = ql;  }
        else if ((j -= N_ACT) < N_ACT)    { src = k;   hi = kh;  lo = kl;  }
        else if ((j -= N_ACT) < N_ACT)    { src = v;   hi = vh;  lo = vl;  }
        else if ((j -= N_ACT) < N_IPW)    { src = ipw; hi = wih; lo = wil; }
        else { j -= N_IPW;                  src = opw; hi = woh; lo = wol; }
        float4 val = src[j];
        u32 h0, l0, h1, l1;
        pack2hl(val.x, val.y, h0, l0);
        pack2hl(val.z, val.w, h1, l1);
        hi[j] = make_uint2(h0, h1);
        lo[j] = make_uint2(l0, l1);
    }
}

// ---------------------------------------------------------------------------
// bf16x3 HMMA GEMM core (device fn; proven R11/R12 body, tile 128x128, BK=16,
// 4-stage cp.async).  m0/n0 = block tile origin; all pointers pre-offset.
// ---------------------------------------------------------------------------
#define STAGE_B 24576u

template<bool SPLIT>
__device__ __forceinline__
void gemm_core(const __nv_bfloat16* __restrict__ Ahi, const __nv_bfloat16* __restrict__ Alo,
               const __nv_bfloat16* __restrict__ Whi, const __nv_bfloat16* __restrict__ Wlo,
               const float* __restrict__ bias, float* __restrict__ out,
               __nv_bfloat16* __restrict__ oh, __nv_bfloat16* __restrict__ ol,
               int N, int K, int m0, int n0)
{
    extern __shared__ __align__(16) char dsm[];
    const u32 sb  = (u32)__cvta_generic_to_shared(dsm);
    const int tid = threadIdx.x;

    auto load_stage = [&](int kt) {
        const u32 base = sb + (u32)(kt & 3) * STAGE_B;
        const int kofs = kt * 16;
        #pragma unroll
        for (int t = 0; t < 2; t++) {
            int j = tid + t * 256;
            int arr = j >> 8, r = (j >> 1) & 127, c = j & 1;
            const __nv_bfloat16* gp = (arr ? Alo : Ahi) + (size_t)(m0 + r) * K + kofs + c * 8;
            cpa16(base + arr * 6144 + r * 48 + c * 16, gp);
        }
        #pragma unroll
        for (int t = 0; t < 2; t++) {
            int j = tid + t * 256;
            int arr = j >> 8, r = (j >> 1) & 127, c = j & 1;
            const __nv_bfloat16* gp = (arr ? Wlo : Whi) + (size_t)(n0 + r) * K + kofs + c * 8;
            cpa16(base + 12288 + arr * 6144 + r * 48 + c * 16, gp);
        }
        CP_COMMIT();
    };

    load_stage(0);
    load_stage(1);
    load_stage(2);

    const int wid  = tid >> 5, lane = tid & 31;
    const int wm   = (wid & 1) << 6;
    const int wn   = (wid >> 1) << 5;

    const u32 a_off = (u32)((wm + (lane & 7) + ((lane >> 3) & 1) * 8) * 48 + (lane >> 4) * 16);
    const u32 b_off = (u32)((wn + (lane & 7) + (lane >> 4) * 8) * 48 + ((lane >> 3) & 1) * 16);

    float acc[4][4][4] = {};

    const int nk = K >> 4;
    for (int kt = 0; kt < nk; kt++) {
        if (kt + 3 < nk) { CP_WAIT(2); } else { CP_WAIT(0); }
        __syncthreads();

        const u32 base = sb + (u32)(kt & 3) * STAGE_B;
        u32 af[4][4], bh[2][4], bl[2][4];

        #pragma unroll
        for (int mf = 0; mf < 4; mf++) ldsm4(af[mf], base + 6144 + a_off + mf * 768);
        #pragma unroll
        for (int pf = 0; pf < 2; pf++) ldsm4(bh[pf], base + 12288 + b_off + pf * 768);
        #pragma unroll
        for (int mf = 0; mf < 4; mf++)
            #pragma unroll
            for (int nf = 0; nf < 4; nf++)
                mma_bf16(acc[mf][nf], af[mf], bh[nf >> 1][(nf & 1) * 2], bh[nf >> 1][(nf & 1) * 2 + 1]);

        #pragma unroll
        for (int mf = 0; mf < 4; mf++) ldsm4(af[mf], base + a_off + mf * 768);
        #pragma unroll
        for (int mf = 0; mf < 4; mf++)
            #pragma unroll
            for (int nf = 0; nf < 4; nf++)
                mma_bf16(acc[mf][nf], af[mf], bh[nf >> 1][(nf & 1) * 2], bh[nf >> 1][(nf & 1) * 2 + 1]);

        #pragma unroll
        for (int pf = 0; pf < 2; pf++) ldsm4(bl[pf], base + 18432 + b_off + pf * 768);
        #pragma unroll
        for (int mf = 0; mf < 4; mf++)
            #pragma unroll
            for (int nf = 0; nf < 4; nf++)
                mma_bf16(acc[mf][nf], af[mf], bl[nf >> 1][(nf & 1) * 2], bl[nf >> 1][(nf & 1) * 2 + 1]);

        if (kt + 3 < nk) load_stage(kt + 3);
    }

    const int gr  = lane >> 2;
    const int gc2 = (lane & 3) * 2;
    #pragma unroll
    for (int mf = 0; mf < 4; mf++) {
        int row0 = m0 + wm + mf * 16 + gr;
        #pragma unroll
        for (int nf = 0; nf < 4; nf++) {
            int col = n0 + wn + nf * 8 + gc2;
            float2 bv = *(const float2*)(bias + col);
            float v00 = acc[mf][nf][0] + bv.x, v01 = acc[mf][nf][1] + bv.y;
            float v10 = acc[mf][nf][2] + bv.x, v11 = acc[mf][nf][3] + bv.y;
            if (SPLIT) {
                u32 h0, l0, h1, l1;
                pack2hl(v00, v01, h0, l0);
                pack2hl(v10, v11, h1, l1);
                *(u32*)(oh + (size_t)row0 * N + col)       = h0;
                *(u32*)(ol + (size_t)row0 * N + col)       = l0;
                *(u32*)(oh + (size_t)(row0 + 8) * N + col) = h1;
                *(u32*)(ol + (size_t)(row0 + 8) * N + col) = l1;
            } else {
                *(float2*)(out + (size_t)row0 * N + col)       = make_float2(v00, v01);
                *(float2*)(out + (size_t)(row0 + 8) * N + col) = make_float2(v10, v11);
            }
        }
    }
}

// Plain GEMM kernel (Q projection / output projection)
template<bool SPLIT>
__global__ __launch_bounds__(256, 2)
void gemm_mma(const __nv_bfloat16* __restrict__ Ahi, const __nv_bfloat16* __restrict__ Alo,
              const __nv_bfloat16* __restrict__ Whi, const __nv_bfloat16* __restrict__ Wlo,
              const float* __restrict__ bias, float* __restrict__ out,
              __nv_bfloat16* __restrict__ oh, __nv_bfloat16* __restrict__ ol,
              int N, int K)
{
    gemm_core<SPLIT>(Ahi, Alo, Whi, Wlo, bias, out, oh, ol, N, K,
                     blockIdx.y * 128, blockIdx.x * 128);
}

// Merged K+V projection: grid (8, 64). bx<4 -> K-proj block, bx>=4 -> V-proj.
__global__ __launch_bounds__(256, 2)
void gemm_mma_kv(const float* __restrict__ ipb)
{
    const int bx  = blockIdx.x;
    const bool isV = bx >= 4;
    const int nb  = bx & 3;
    const size_t wofs = (size_t)(AT_C + (isV ? AT_KV : 0)) * AT_C;
    gemm_core<true>(isV ? g_vh : g_kh, isV ? g_vl : g_kl,
                    g_wih + wofs, g_wil + wofs,
                    ipb + AT_C + (isV ? AT_KV : 0), nullptr,
                    isV ? g_xvh : g_xkh, isV ? g_xvl : g_xkl,
                    AT_KV, AT_C, blockIdx.y * 128, nb * 128);
}

// ---------------------------------------------------------------------------
// Tensor-core flash attention (causal, GQA), bf16x3, BM=64, occ 2.
// R13: pipelined K/V loads — K(j+1) issued after S reads K(j) (hides under
// softmax+PV); V(j+1) after PV (hides under next S). wait_group(1) ordering.
// ---------------------------------------------------------------------------
__global__ __launch_bounds__(128, 2)
void attn_tc_kernel()
{
    extern __shared__ __align__(16) __nv_bfloat16 smx[];
    const u32 sb = (u32)__cvta_generic_to_shared(smx);
    const u32 QH = 0, QL = 17408, KH = 34816, KL = 52224, VH = 69632, VL = 87040;

    const int tid  = threadIdx.x;
    const int wid  = tid >> 5, lane = tid & 31;
    const int bx   = blockIdx.x;
    const int b    = bx >> 4;
    const int hd   = bx & 15;
    const int hkv  = hd & 3;
    const int qb   = 31 - blockIdx.y;          // heavy blocks first
    const int q0   = qb * 64;

    const __nv_bfloat16* qhp = g_xqh + ((size_t)b * AT_T + q0) * AT_C + hd * AT_D;
    const __nv_bfloat16* qlp = g_xql + ((size_t)b * AT_T + q0) * AT_C + hd * AT_D;
    const __nv_bfloat16* khp = g_xkh + (size_t)b * AT_T * AT_KV + hkv * AT_D;
    const __nv_bfloat16* klp = g_xkl + (size_t)b * AT_T * AT_KV + hkv * AT_D;
    const __nv_bfloat16* vhp = g_xvh + (size_t)b * AT_T * AT_KV + hkv * AT_D;
    const __nv_bfloat16* vlp = g_xvl + (size_t)b * AT_T * AT_KV + hkv * AT_D;

    auto load_K = [&](int j) {
        if (j <= qb) {
            for (int i = tid; i < 1024; i += 128) {
                int row = i >> 4, cc = (i & 15) << 3;
                size_t g = (size_t)(j * 64 + row) * AT_KV + cc;
                u32 so = row * 272 + cc * 2;
                cpa16(sb + KH + so, khp + g);
                cpa16(sb + KL + so, klp + g);
            }
        }
        CP_COMMIT();
    };
    auto load_V = [&](int j) {
        if (j <= qb) {
            for (int i = tid; i < 1024; i += 128) {
                int row = i >> 4, cc = (i & 15) << 3;
                size_t g = (size_t)(j * 64 + row) * AT_KV + cc;
                u32 so = row * 272 + cc * 2;
                cpa16(sb + VH + so, vhp + g);
                cpa16(sb + VL + so, vlp + g);
            }
        }
        CP_COMMIT();
    };

    // Q tile (64 x 128 halves, hi+lo)
    for (int i = tid; i < 1024; i += 128) {
        int row = i >> 4, cc = (i & 15) << 3;
        size_t g = (size_t)row * AT_C + cc;
        cpa16(sb + QH + row * 272 + cc * 2, qhp + g);
        cpa16(sb + QL + row * 272 + cc * 2, qlp + g);
    }
    CP_COMMIT();
    load_K(0);
    load_V(0);

    const int wq = wid * 16;
    const int gr = lane >> 2;
    const int qrow0 = q0 + wq + gr;
    const int qrow1 = qrow0 + 8;

    const u32 a_off = (u32)((wq + (lane & 7) + ((lane >> 3) & 1) * 8) * 272 + (lane >> 4) * 16);
    const u32 b_off = (u32)(((lane & 7) + (lane >> 4) * 8) * 272 + ((lane >> 3) & 1) * 16);
    const u32 v_off = (u32)(((lane & 7) + ((lane >> 3) & 1) * 8) * 272 + (lane >> 4) * 16);

    float o[16][4];
    #pragma unroll
    for (int nf = 0; nf < 16; nf++)
        #pragma unroll
        for (int k = 0; k < 4; k++) o[nf][k] = 0.f;
    float m0 = -1e30f, m1 = -1e30f, l0 = 0.f, l1 = 0.f;

    for (int j = 0; j <= qb; j++) {
        // K(j) (and Q) complete; V(j) may still be in flight
        CP_WAIT(1);
        __syncthreads();

        // ---- S = Q K^T (bf16x3) ----
        float s[8][4];
        #pragma unroll
        for (int nf = 0; nf < 8; nf++)
            #pragma unroll
            for (int k = 0; k < 4; k++) s[nf][k] = 0.f;

        #pragma unroll
        for (int c = 0; c < 8; c++) {
            u32 ah[4], al[4];
            ldsm4(ah, sb + QH + a_off + c * 32);
            ldsm4(al, sb + QL + a_off + c * 32);
            #pragma unroll
            for (int nb = 0; nb < 4; nb++) {
                u32 bh_[4], bl_[4];
                u32 ka = b_off + nb * 4352 + c * 32;
                ldsm4(bh_, sb + KH + ka);
                ldsm4(bl_, sb + KL + ka);
                mma_bf16(s[2 * nb],     al, bh_[0], bh_[1]);
                mma_bf16(s[2 * nb + 1], al, bh_[2], bh_[3]);
                mma_bf16(s[2 * nb],     ah, bl_[0], bl_[1]);
                mma_bf16(s[2 * nb + 1], ah, bl_[2], bl_[3]);
                mma_bf16(s[2 * nb],     ah, bh_[0], bh_[1]);
                mma_bf16(s[2 * nb + 1], ah, bh_[2], bh_[3]);
            }
        }

        __syncthreads();            // all warps done reading K(j)
        load_K(j + 1);              // hides under softmax + PV

        // ---- online softmax ----
        const bool maskt = (j == qb);
        const int colb = j * 64 + 2 * (lane & 3);
        float mx0 = -1e30f, mx1 = -1e30f;
        #pragma unroll
        for (int nf = 0; nf < 8; nf++) {
            int c0 = colb + 8 * nf;
            s[nf][0] *= AT_SCALE; s[nf][1] *= AT_SCALE;
            s[nf][2] *= AT_SCALE; s[nf][3] *= AT_SCALE;
            if (maskt) {
                if (c0     > qrow0) s[nf][0] = -1e30f;
                if (c0 + 1 > qrow0) s[nf][1] = -1e30f;
                if (c0     > qrow1) s[nf][2] = -1e30f;
                if (c0 + 1 > qrow1) s[nf][3] = -1e30f;
            }
            mx0 = fmaxf(mx0, fmaxf(s[nf][0], s[nf][1]));
            mx1 = fmaxf(mx1, fmaxf(s[nf][2], s[nf][3]));
        }
        mx0 = fmaxf(mx0, __shfl_xor_sync(0xffffffffu, mx0, 1));
        mx0 = fmaxf(mx0, __shfl_xor_sync(0xffffffffu, mx0, 2));
        mx1 = fmaxf(mx1, __shfl_xor_sync(0xffffffffu, mx1, 1));
        mx1 = fmaxf(mx1, __shfl_xor_sync(0xffffffffu, mx1, 2));

        float nm0 = fmaxf(m0, mx0), nm1 = fmaxf(m1, mx1);
        float corr0 = __expf(m0 - nm0), corr1 = __expf(m1 - nm1);
        m0 = nm0; m1 = nm1;

        float rs0 = 0.f, rs1 = 0.f;
        #pragma unroll
        for (int nf = 0; nf < 8; nf++) {
            s[nf][0] = __expf(s[nf][0] - m0); rs0 += s[nf][0];
            s[nf][1] = __expf(s[nf][1] - m0); rs0 += s[nf][1];
            s[nf][2] = __expf(s[nf][2] - m1); rs1 += s[nf][2];
            s[nf][3] = __expf(s[nf][3] - m1); rs1 += s[nf][3];
        }
        rs0 += __shfl_xor_sync(0xffffffffu, rs0, 1);
        rs0 += __shfl_xor_sync(0xffffffffu, rs0, 2);
        rs1 += __shfl_xor_sync(0xffffffffu, rs1, 1);
        rs1 += __shfl_xor_sync(0xffffffffu, rs1, 2);
        l0 = l0 * corr0 + rs0;
        l1 = l1 * corr1 + rs1;

        #pragma unroll
        for (int nf = 0; nf < 16; nf++) {
            o[nf][0] *= corr0; o[nf][1] *= corr0;
            o[nf][2] *= corr1; o[nf][3] *= corr1;
        }

        // V(j) complete (K(j+1) may still be in flight)
        CP_WAIT(1);
        __syncthreads();

        // ---- O += P V (bf16x3) ----
        #pragma unroll
        for (int c = 0; c < 4; c++) {
            u32 aph[4], apl[4];
            pack2hl(s[2 * c][0],     s[2 * c][1],     aph[0], apl[0]);
            pack2hl(s[2 * c][2],     s[2 * c][3],     aph[1], apl[1]);
            pack2hl(s[2 * c + 1][0], s[2 * c + 1][1], aph[2], apl[2]);
            pack2hl(s[2 * c + 1][2], s[2 * c + 1][3], aph[3], apl[3]);
            #pragma unroll
            for (int nb = 0; nb < 8; nb++) {
                u32 vh_[4], vl_[4];
                u32 va = v_off + c * 4352 + nb * 32;
                ldsm4t(vh_, sb + VH + va);
                ldsm4t(vl_, sb + VL + va);
                mma_bf16(o[2 * nb],     aph, vh_[0], vh_[1]);
                mma_bf16(o[2 * nb + 1], aph, vh_[2], vh_[3]);
                mma_bf16(o[2 * nb],     aph, vl_[0], vl_[1]);
                mma_bf16(o[2 * nb + 1], aph, vl_[2], vl_[3]);
                mma_bf16(o[2 * nb],     apl, vh_[0], vh_[1]);
                mma_bf16(o[2 * nb + 1], apl, vh_[2], vh_[3]);
            }
        }

        __syncthreads();            // all warps done reading V(j)
        load_V(j + 1);              // hides under next S
    }

    // ---- epilogue: O/l -> bf16 hi/lo ----
    const float inv0 = 1.0f / l0, inv1 = 1.0f / l1;
    const size_t obase = (size_t)b * AT_T * AT_C + (size_t)hd * AT_D;
    #pragma unroll
    for (int nf = 0; nf < 16; nf++) {
        int d = nf * 8 + 2 * (lane & 3);
        u32 h0, lo0, h1, lo1;
        pack2hl(o[nf][0] * inv0, o[nf][1] * inv0, h0, lo0);
        pack2hl(o[nf][2] * inv1, o[nf][3] * inv1, h1, lo1);
        size_t i0 = obase + (size_t)qrow0 * AT_C + d;
        size_t i1 = obase + (size_t)qrow1 * AT_C + d;
        *(u32*)(g_xoh + i0) = h0;  *(u32*)(g_xol + i0) = lo0;
        *(u32*)(g_xoh + i1) = h1;  *(u32*)(g_xol + i1) = lo1;
    }
}

// ---------------------------------------------------------------------------
// Launch: fused split -> Q proj + merged KV proj -> TC attention -> out proj
// ---------------------------------------------------------------------------
extern "C" void kernel_launch(void* const* d_in, const int* in_sizes, int n_in,
                              void* d_out, int out_size)
{
    const float* q   = (const float*)d_in[0];
    const float* k   = (const float*)d_in[1];
    const float* v   = (const float*)d_in[2];
    const float* ipw = (const float*)d_in[3];  // (3072, 2048)
    const float* ipb = (const float*)d_in[4];  // (3072,)
    const float* opw = (const float*)d_in[5];  // (2048, 2048)
    const float* opb = (const float*)d_in[6];  // (2048,)
    float* out = (float*)d_out;

    __nv_bfloat16 *qh, *ql, *kh, *kl, *vh, *vl, *wih, *wil, *woh, *wol;
    __nv_bfloat16 *xqh, *xql, *xoh, *xol;
    cudaGetSymbolAddress((void**)&qh, g_qh);   cudaGetSymbolAddress((void**)&ql, g_ql);
    cudaGetSymbolAddress((void**)&kh, g_kh);   cudaGetSymbolAddress((void**)&kl, g_kl);
    cudaGetSymbolAddress((void**)&vh, g_vh);   cudaGetSymbolAddress((void**)&vl, g_vl);
    cudaGetSymbolAddress((void**)&wih, g_wih); cudaGetSymbolAddress((void**)&wil, g_wil);
    cudaGetSymbolAddress((void**)&woh, g_woh); cudaGetSymbolAddress((void**)&wol, g_wol);
    cudaGetSymbolAddress((void**)&xqh, g_xqh); cudaGetSymbolAddress((void**)&xql, g_xql);
    cudaGetSymbolAddress((void**)&xoh, g_xoh); cudaGetSymbolAddress((void**)&xol, g_xol);

    const int attn_smem = 104448;  // (64+64+64) rows x 272 B x hi/lo
    cudaFuncSetAttribute(attn_tc_kernel, cudaFuncAttributeMaxDynamicSharedMemorySize, attn_smem);
    const int gemm_smem = 4 * STAGE_B;  // 98304
    cudaFuncSetAttribute(gemm_mma<true>,  cudaFuncAttributeMaxDynamicSharedMemorySize, gemm_smem);
    cudaFuncSetAttribute(gemm_mma<false>, cudaFuncAttributeMaxDynamicSharedMemorySize, gemm_smem);
    cudaFuncSetAttribute(gemm_mma_kv,     cudaFuncAttributeMaxDynamicSharedMemorySize, gemm_smem);

    dim3 blk(256);
    const int M_BLK = (AT_B * AT_T) / 128;  // 64

    // Fused prep: split inputs + weights into bf16 hi/lo (one launch)
    split_all_kernel<<<4096, 256>>>((const float4*)q, (const float4*)k, (const float4*)v,
                                    (const float4*)ipw, (const float4*)opw,
                                    (uint2*)qh, (uint2*)ql, (uint2*)kh, (uint2*)kl,
                                    (uint2*)vh, (uint2*)vl, (uint2*)wih, (uint2*)wil,
                                    (uint2*)woh, (uint2*)wol);

    // Q projection
    gemm_mma<true><<<dim3(AT_C / 128, M_BLK), blk, gemm_smem>>>(
        qh, ql, wih, wil, ipb, nullptr, xqh, xql, AT_C, AT_C);
    // Merged K+V projection (one launch, grid 8 x 64)
    gemm_mma_kv<<<dim3(8, M_BLK), blk, gemm_smem>>>(ipb);

    // Tensor-core causal GQA flash attention (BM=64, occ 2, pipelined K/V)
    attn_tc_kernel<<<dim3(AT_B * AT_H, AT_T / 64), dim3(128), attn_smem>>>();

    // Output projection (fp32 out)
    gemm_mma<false><<<dim3(AT_C / 128, M_BLK), blk, gemm_smem>>>(
        xoh, xol, woh, wol, opb, out, nullptr, nullptr, AT_C, AT_C);
}

// round 14
// speedup vs baseline: 2.7885x; 1.0190x over previous
#include <cuda_runtime.h>
#include <cuda_bf16.h>
#include <cstdint>
#include <cstddef>

// Problem constants: B=4, T=2048, C=2048, H=16, G=4, HKV=4, D=128, KV=512
#define AT_B   4
#define AT_T   2048
#define AT_C   2048
#define AT_KV  512
#define AT_D   128
#define AT_H   16
#define AT_HKV 4
#define AT_SCALE 0.08838834764831845f  // 1/sqrt(128)

typedef unsigned long long u64;
typedef unsigned int u32;

// ---------------------------------------------------------------------------
// Common helpers
// ---------------------------------------------------------------------------
__device__ __forceinline__ void pack2hl(float x, float y, u32& h, u32& l) {
    __nv_bfloat162 hv = __float22bfloat162_rn(make_float2(x, y));
    float lx = x - __low2float(hv), ly = y - __high2float(hv);
    __nv_bfloat162 lv = __float22bfloat162_rn(make_float2(lx, ly));
    h = *reinterpret_cast<u32*>(&hv);
    l = *reinterpret_cast<u32*>(&lv);
}

// ---- legacy mma helpers (proven R8-R13) ----
__device__ __forceinline__ void ldsm4(u32* r, u32 addr) {
    asm volatile("ldmatrix.sync.aligned.m8n8.x4.shared.b16 {%0,%1,%2,%3}, [%4];"
                 : "=r"(r[0]), "=r"(r[1]), "=r"(r[2]), "=r"(r[3]) : "r"(addr));
}
__device__ __forceinline__ void ldsm4t(u32* r, u32 addr) {
    asm volatile("ldmatrix.sync.aligned.m8n8.x4.trans.shared.b16 {%0,%1,%2,%3}, [%4];"
                 : "=r"(r[0]), "=r"(r[1]), "=r"(r[2]), "=r"(r[3]) : "r"(addr));
}
__device__ __forceinline__ void mma_bf16(float* d, const u32* a, u32 b0, u32 b1) {
    asm volatile("mma.sync.aligned.m16n8k16.row.col.f32.bf16.bf16.f32 "
                 "{%0,%1,%2,%3}, {%4,%5,%6,%7}, {%8,%9}, {%0,%1,%2,%3};"
                 : "+f"(d[0]), "+f"(d[1]), "+f"(d[2]), "+f"(d[3])
                 : "r"(a[0]), "r"(a[1]), "r"(a[2]), "r"(a[3]), "r"(b0), "r"(b1));
}

// ---- cp.async helpers ----
__device__ __forceinline__ void cpa16(u32 s, const void* g) {
    asm volatile("cp.async.cg.shared.global [%0], [%1], 16;" :: "r"(s), "l"(g) : "memory");
}
#define CP_COMMIT() asm volatile("cp.async.commit_group;" ::: "memory")
#define CP_WAIT(n)  asm volatile("cp.async.wait_group %0;" :: "n"(n) : "memory")

// ---------------------------------------------------------------------------
// Scratch (allocation-free rule: __device__ globals)
// ---------------------------------------------------------------------------
__device__ __nv_bfloat16 g_qh[AT_B * AT_T * AT_C], g_ql[AT_B * AT_T * AT_C];
__device__ __nv_bfloat16 g_kh[AT_B * AT_T * AT_C], g_kl[AT_B * AT_T * AT_C];
__device__ __nv_bfloat16 g_vh[AT_B * AT_T * AT_C], g_vl[AT_B * AT_T * AT_C];
__device__ __nv_bfloat16 g_wih[(AT_C + 2 * AT_KV) * AT_C], g_wil[(AT_C + 2 * AT_KV) * AT_C];
__device__ __nv_bfloat16 g_woh[AT_C * AT_C], g_wol[AT_C * AT_C];
__device__ __nv_bfloat16 g_xqh[AT_B * AT_T * AT_C],  g_xql[AT_B * AT_T * AT_C];
__device__ __nv_bfloat16 g_xkh[AT_B * AT_T * AT_KV], g_xkl[AT_B * AT_T * AT_KV];
__device__ __nv_bfloat16 g_xvh[AT_B * AT_T * AT_KV], g_xvl[AT_B * AT_T * AT_KV];
__device__ __nv_bfloat16 g_xoh[AT_B * AT_T * AT_C], g_xol[AT_B * AT_T * AT_C];

// ---------------------------------------------------------------------------
// Fused fp32 -> (bf16 hi, bf16 lo) split over all 5 tensors (one launch)
// ---------------------------------------------------------------------------
#define N_ACT (AT_B * AT_T * AT_C / 4)
#define N_IPW ((AT_C + 2 * AT_KV) * AT_C / 4)
#define N_OPW (AT_C * AT_C / 4)

__global__ void split_all_kernel(const float4* __restrict__ q, const float4* __restrict__ k,
                                 const float4* __restrict__ v, const float4* __restrict__ ipw,
                                 const float4* __restrict__ opw,
                                 uint2* qh, uint2* ql, uint2* kh, uint2* kl,
                                 uint2* vh, uint2* vl, uint2* wih, uint2* wil,
                                 uint2* woh, uint2* wol)
{
    const int total = 3 * N_ACT + N_IPW + N_OPW;
    for (int i = blockIdx.x * blockDim.x + threadIdx.x; i < total; i += gridDim.x * blockDim.x) {
        const float4* src; uint2 *hi, *lo; int j = i;
        if (j < N_ACT)                    { src = q;   hi = qh;  lo = ql;  }
        else if ((j -= N_ACT) < N_ACT)    { src = k;   hi = kh;  lo = kl;  }
        else if ((j -= N_ACT) < N_ACT)    { src = v;   hi = vh;  lo = vl;  }
        else if ((j -= N_ACT) < N_IPW)    { src = ipw; hi = wih; lo = wil; }
        else { j -= N_IPW;                  src = opw; hi = woh; lo = wol; }
        float4 val = src[j];
        u32 h0, l0, h1, l1;
        pack2hl(val.x, val.y, h0, l0);
        pack2hl(val.z, val.w, h1, l1);
        hi[j] = make_uint2(h0, h1);
        lo[j] = make_uint2(l0, l1);
    }
}

// ---------------------------------------------------------------------------
// bf16x3 HMMA GEMM core (proven R11-R13 body; tile 128x128, BK=16, 4-stage
// cp.async). 'scl' is applied to (acc+bias) in the epilogue (Q pre-scaling).
// ---------------------------------------------------------------------------
#define STAGE_B 24576u

template<bool SPLIT>
__device__ __forceinline__
void gemm_core(const __nv_bfloat16* __restrict__ Ahi, const __nv_bfloat16* __restrict__ Alo,
               const __nv_bfloat16* __restrict__ Whi, const __nv_bfloat16* __restrict__ Wlo,
               const float* __restrict__ bias, float* __restrict__ out,
               __nv_bfloat16* __restrict__ oh, __nv_bfloat16* __restrict__ ol,
               int N, int K, int m0, int n0, float scl)
{
    extern __shared__ __align__(16) char dsm[];
    const u32 sb  = (u32)__cvta_generic_to_shared(dsm);
    const int tid = threadIdx.x;

    auto load_stage = [&](int kt) {
        const u32 base = sb + (u32)(kt & 3) * STAGE_B;
        const int kofs = kt * 16;
        #pragma unroll
        for (int t = 0; t < 2; t++) {
            int j = tid + t * 256;
            int arr = j >> 8, r = (j >> 1) & 127, c = j & 1;
            const __nv_bfloat16* gp = (arr ? Alo : Ahi) + (size_t)(m0 + r) * K + kofs + c * 8;
            cpa16(base + arr * 6144 + r * 48 + c * 16, gp);
        }
        #pragma unroll
        for (int t = 0; t < 2; t++) {
            int j = tid + t * 256;
            int arr = j >> 8, r = (j >> 1) & 127, c = j & 1;
            const __nv_bfloat16* gp = (arr ? Wlo : Whi) + (size_t)(n0 + r) * K + kofs + c * 8;
            cpa16(base + 12288 + arr * 6144 + r * 48 + c * 16, gp);
        }
        CP_COMMIT();
    };

    load_stage(0);
    load_stage(1);
    load_stage(2);

    const int wid  = tid >> 5, lane = tid & 31;
    const int wm   = (wid & 1) << 6;
    const int wn   = (wid >> 1) << 5;

    const u32 a_off = (u32)((wm + (lane & 7) + ((lane >> 3) & 1) * 8) * 48 + (lane >> 4) * 16);
    const u32 b_off = (u32)((wn + (lane & 7) + (lane >> 4) * 8) * 48 + ((lane >> 3) & 1) * 16);

    float acc[4][4][4] = {};

    const int nk = K >> 4;
    for (int kt = 0; kt < nk; kt++) {
        if (kt + 3 < nk) { CP_WAIT(2); } else { CP_WAIT(0); }
        __syncthreads();

        const u32 base = sb + (u32)(kt & 3) * STAGE_B;
        u32 af[4][4], bh[2][4], bl[2][4];

        #pragma unroll
        for (int mf = 0; mf < 4; mf++) ldsm4(af[mf], base + 6144 + a_off + mf * 768);
        #pragma unroll
        for (int pf = 0; pf < 2; pf++) ldsm4(bh[pf], base + 12288 + b_off + pf * 768);
        #pragma unroll
        for (int mf = 0; mf < 4; mf++)
            #pragma unroll
            for (int nf = 0; nf < 4; nf++)
                mma_bf16(acc[mf][nf], af[mf], bh[nf >> 1][(nf & 1) * 2], bh[nf >> 1][(nf & 1) * 2 + 1]);

        #pragma unroll
        for (int mf = 0; mf < 4; mf++) ldsm4(af[mf], base + a_off + mf * 768);
        #pragma unroll
        for (int mf = 0; mf < 4; mf++)
            #pragma unroll
            for (int nf = 0; nf < 4; nf++)
                mma_bf16(acc[mf][nf], af[mf], bh[nf >> 1][(nf & 1) * 2], bh[nf >> 1][(nf & 1) * 2 + 1]);

        #pragma unroll
        for (int pf = 0; pf < 2; pf++) ldsm4(bl[pf], base + 18432 + b_off + pf * 768);
        #pragma unroll
        for (int mf = 0; mf < 4; mf++)
            #pragma unroll
            for (int nf = 0; nf < 4; nf++)
                mma_bf16(acc[mf][nf], af[mf], bl[nf >> 1][(nf & 1) * 2], bl[nf >> 1][(nf & 1) * 2 + 1]);

        if (kt + 3 < nk) load_stage(kt + 3);
    }

    const int gr  = lane >> 2;
    const int gc2 = (lane & 3) * 2;
    #pragma unroll
    for (int mf = 0; mf < 4; mf++) {
        int row0 = m0 + wm + mf * 16 + gr;
        #pragma unroll
        for (int nf = 0; nf < 4; nf++) {
            int col = n0 + wn + nf * 8 + gc2;
            float2 bv = *(const float2*)(bias + col);
            float v00 = (acc[mf][nf][0] + bv.x) * scl, v01 = (acc[mf][nf][1] + bv.y) * scl;
            float v10 = (acc[mf][nf][2] + bv.x) * scl, v11 = (acc[mf][nf][3] + bv.y) * scl;
            if (SPLIT) {
                u32 h0, l0, h1, l1;
                pack2hl(v00, v01, h0, l0);
                pack2hl(v10, v11, h1, l1);
                *(u32*)(oh + (size_t)row0 * N + col)       = h0;
                *(u32*)(ol + (size_t)row0 * N + col)       = l0;
                *(u32*)(oh + (size_t)(row0 + 8) * N + col) = h1;
                *(u32*)(ol + (size_t)(row0 + 8) * N + col) = l1;
            } else {
                *(float2*)(out + (size_t)row0 * N + col)       = make_float2(v00, v01);
                *(float2*)(out + (size_t)(row0 + 8) * N + col) = make_float2(v10, v11);
            }
        }
    }
}

// Merged Q+K+V projection: grid (24, 64).
//   bx in [0,16)  -> Q proj (N=2048), output pre-scaled by 1/sqrt(D)
//   bx in [16,20) -> K proj (N=512)
//   bx in [20,24) -> V proj (N=512)
__global__ __launch_bounds__(256, 2)
void gemm_mma_proj(const float* __restrict__ ipb)
{
    const int bx = blockIdx.x;
    const __nv_bfloat16 *Ahi, *Alo, *Whi, *Wlo;
    __nv_bfloat16 *oh, *ol;
    const float* bias;
    int N, n0;
    float scl;
    if (bx < 16) {
        Ahi = g_qh; Alo = g_ql; Whi = g_wih; Wlo = g_wil;
        bias = ipb; oh = g_xqh; ol = g_xql; N = AT_C; n0 = bx * 128; scl = AT_SCALE;
    } else if (bx < 20) {
        Ahi = g_kh; Alo = g_kl;
        Whi = g_wih + (size_t)AT_C * AT_C; Wlo = g_wil + (size_t)AT_C * AT_C;
        bias = ipb + AT_C; oh = g_xkh; ol = g_xkl; N = AT_KV; n0 = (bx - 16) * 128; scl = 1.0f;
    } else {
        Ahi = g_vh; Alo = g_vl;
        Whi = g_wih + (size_t)(AT_C + AT_KV) * AT_C; Wlo = g_wil + (size_t)(AT_C + AT_KV) * AT_C;
        bias = ipb + AT_C + AT_KV; oh = g_xvh; ol = g_xvl; N = AT_KV; n0 = (bx - 20) * 128; scl = 1.0f;
    }
    gemm_core<true>(Ahi, Alo, Whi, Wlo, bias, nullptr, oh, ol,
                    N, AT_C, blockIdx.y * 128, n0, scl);
}

// Output projection (fp32 out)
__global__ __launch_bounds__(256, 2)
void gemm_mma_out(const float* __restrict__ opb, float* __restrict__ out)
{
    gemm_core<false>(g_xoh, g_xol, g_woh, g_wol, opb, out, nullptr, nullptr,
                     AT_C, AT_C, blockIdx.y * 128, blockIdx.x * 128, 1.0f);
}

// ---------------------------------------------------------------------------
// Tensor-core flash attention (causal, GQA), bf16x3, BM=64, occ 2.
// R14: Q pre-scaled by 1/sqrt(D) in projection (no scale muls here);
// Q fragments hoisted into registers before the KV loop (tile-invariant).
// ---------------------------------------------------------------------------
__global__ __launch_bounds__(128, 2)
void attn_tc_kernel()
{
    extern __shared__ __align__(16) __nv_bfloat16 smx[];
    const u32 sb = (u32)__cvta_generic_to_shared(smx);
    const u32 QH = 0, QL = 17408, KH = 34816, KL = 52224, VH = 69632, VL = 87040;

    const int tid  = threadIdx.x;
    const int wid  = tid >> 5, lane = tid & 31;
    const int bx   = blockIdx.x;
    const int b    = bx >> 4;
    const int hd   = bx & 15;
    const int hkv  = hd & 3;
    const int qb   = 31 - blockIdx.y;          // heavy blocks first
    const int q0   = qb * 64;

    const __nv_bfloat16* qhp = g_xqh + ((size_t)b * AT_T + q0) * AT_C + hd * AT_D;
    const __nv_bfloat16* qlp = g_xql + ((size_t)b * AT_T + q0) * AT_C + hd * AT_D;
    const __nv_bfloat16* khp = g_xkh + (size_t)b * AT_T * AT_KV + hkv * AT_D;
    const __nv_bfloat16* klp = g_xkl + (size_t)b * AT_T * AT_KV + hkv * AT_D;
    const __nv_bfloat16* vhp = g_xvh + (size_t)b * AT_T * AT_KV + hkv * AT_D;
    const __nv_bfloat16* vlp = g_xvl + (size_t)b * AT_T * AT_KV + hkv * AT_D;

    auto load_K = [&](int j) {
        if (j <= qb) {
            for (int i = tid; i < 1024; i += 128) {
                int row = i >> 4, cc = (i & 15) << 3;
                size_t g = (size_t)(j * 64 + row) * AT_KV + cc;
                u32 so = row * 272 + cc * 2;
                cpa16(sb + KH + so, khp + g);
                cpa16(sb + KL + so, klp + g);
            }
        }
        CP_COMMIT();
    };
    auto load_V = [&](int j) {
        if (j <= qb) {
            for (int i = tid; i < 1024; i += 128) {
                int row = i >> 4, cc = (i & 15) << 3;
                size_t g = (size_t)(j * 64 + row) * AT_KV + cc;
                u32 so = row * 272 + cc * 2;
                cpa16(sb + VH + so, vhp + g);
                cpa16(sb + VL + so, vlp + g);
            }
        }
        CP_COMMIT();
    };

    // Q tile (64 x 128 halves, hi+lo)
    for (int i = tid; i < 1024; i += 128) {
        int row = i >> 4, cc = (i & 15) << 3;
        size_t g = (size_t)row * AT_C + cc;
        cpa16(sb + QH + row * 272 + cc * 2, qhp + g);
        cpa16(sb + QL + row * 272 + cc * 2, qlp + g);
    }
    CP_COMMIT();
    load_K(0);
    load_V(0);

    const int wq = wid * 16;
    const int gr = lane >> 2;
    const int qrow0 = q0 + wq + gr;
    const int qrow1 = qrow0 + 8;

    const u32 a_off = (u32)((wq + (lane & 7) + ((lane >> 3) & 1) * 8) * 272 + (lane >> 4) * 16);
    const u32 b_off = (u32)(((lane & 7) + (lane >> 4) * 8) * 272 + ((lane >> 3) & 1) * 16);
    const u32 v_off = (u32)(((lane & 7) + ((lane >> 3) & 1) * 8) * 272 + (lane >> 4) * 16);

    // Hoist Q fragments (tile-invariant) into registers
    u32 qah[8][4], qal[8][4];
    CP_WAIT(2);          // Q group complete (K0/V0 may be in flight)
    __syncthreads();
    #pragma unroll
    for (int c = 0; c < 8; c++) {
        ldsm4(qah[c], sb + QH + a_off + c * 32);
        ldsm4(qal[c], sb + QL + a_off + c * 32);
    }

    float o[16][4];
    #pragma unroll
    for (int nf = 0; nf < 16; nf++)
        #pragma unroll
        for (int k = 0; k < 4; k++) o[nf][k] = 0.f;
    float m0 = -1e30f, m1 = -1e30f, l0 = 0.f, l1 = 0.f;

    for (int j = 0; j <= qb; j++) {
        // K(j) complete; V(j) may still be in flight
        CP_WAIT(1);
        __syncthreads();

        // ---- S = Q K^T (bf16x3; Q from registers) ----
        float s[8][4];
        #pragma unroll
        for (int nf = 0; nf < 8; nf++)
            #pragma unroll
            for (int k = 0; k < 4; k++) s[nf][k] = 0.f;

        #pragma unroll
        for (int c = 0; c < 8; c++) {
            #pragma unroll
            for (int nb = 0; nb < 4; nb++) {
                u32 bh_[4], bl_[4];
                u32 ka = b_off + nb * 4352 + c * 32;
                ldsm4(bh_, sb + KH + ka);
                ldsm4(bl_, sb + KL + ka);
                mma_bf16(s[2 * nb],     qal[c], bh_[0], bh_[1]);
                mma_bf16(s[2 * nb + 1], qal[c], bh_[2], bh_[3]);
                mma_bf16(s[2 * nb],     qah[c], bl_[0], bl_[1]);
                mma_bf16(s[2 * nb + 1], qah[c], bl_[2], bl_[3]);
                mma_bf16(s[2 * nb],     qah[c], bh_[0], bh_[1]);
                mma_bf16(s[2 * nb + 1], qah[c], bh_[2], bh_[3]);
            }
        }

        __syncthreads();            // all warps done reading K(j)
        load_K(j + 1);              // hides under softmax + PV

        // ---- online softmax (Q pre-scaled; no scale muls) ----
        const bool maskt = (j == qb);
        const int colb = j * 64 + 2 * (lane & 3);
        float mx0 = -1e30f, mx1 = -1e30f;
        #pragma unroll
        for (int nf = 0; nf < 8; nf++) {
            int c0 = colb + 8 * nf;
            if (maskt) {
                if (c0     > qrow0) s[nf][0] = -1e30f;
                if (c0 + 1 > qrow0) s[nf][1] = -1e30f;
                if (c0     > qrow1) s[nf][2] = -1e30f;
                if (c0 + 1 > qrow1) s[nf][3] = -1e30f;
            }
            mx0 = fmaxf(mx0, fmaxf(s[nf][0], s[nf][1]));
            mx1 = fmaxf(mx1, fmaxf(s[nf][2], s[nf][3]));
        }
        mx0 = fmaxf(mx0, __shfl_xor_sync(0xffffffffu, mx0, 1));
        mx0 = fmaxf(mx0, __shfl_xor_sync(0xffffffffu, mx0, 2));
        mx1 = fmaxf(mx1, __shfl_xor_sync(0xffffffffu, mx1, 1));
        mx1 = fmaxf(mx1, __shfl_xor_sync(0xffffffffu, mx1, 2));

        float nm0 = fmaxf(m0, mx0), nm1 = fmaxf(m1, mx1);
        float corr0 = __expf(m0 - nm0), corr1 = __expf(m1 - nm1);
        m0 = nm0; m1 = nm1;

        float rs0 = 0.f, rs1 = 0.f;
        #pragma unroll
        for (int nf = 0; nf < 8; nf++) {
            s[nf][0] = __expf(s[nf][0] - m0); rs0 += s[nf][0];
            s[nf][1] = __expf(s[nf][1] - m0); rs0 += s[nf][1];
            s[nf][2] = __expf(s[nf][2] - m1); rs1 += s[nf][2];
            s[nf][3] = __expf(s[nf][3] - m1); rs1 += s[nf][3];
        }
        rs0 += __shfl_xor_sync(0xffffffffu, rs0, 1);
        rs0 += __shfl_xor_sync(0xffffffffu, rs0, 2);
        rs1 += __shfl_xor_sync(0xffffffffu, rs1, 1);
        rs1 += __shfl_xor_sync(0xffffffffu, rs1, 2);
        l0 = l0 * corr0 + rs0;
        l1 = l1 * corr1 + rs1;

        #pragma unroll
        for (int nf = 0; nf < 16; nf++) {
            o[nf][0] *= corr0; o[nf][1] *= corr0;
            o[nf][2] *= corr1; o[nf][3] *= corr1;
        }

        // V(j) complete (K(j+1) may still be in flight)
        CP_WAIT(1);
        __syncthreads();

        // ---- O += P V (bf16x3) ----
        #pragma unroll
        for (int c = 0; c < 4; c++) {
            u32 aph[4], apl[4];
            pack2hl(s[2 * c][0],     s[2 * c][1],     aph[0], apl[0]);
            pack2hl(s[2 * c][2],     s[2 * c][3],     aph[1], apl[1]);
            pack2hl(s[2 * c + 1][0], s[2 * c + 1][1], aph[2], apl[2]);
            pack2hl(s[2 * c + 1][2], s[2 * c + 1][3], aph[3], apl[3]);
            #pragma unroll
            for (int nb = 0; nb < 8; nb++) {
                u32 vh_[4], vl_[4];
                u32 va = v_off + c * 4352 + nb * 32;
                ldsm4t(vh_, sb + VH + va);
                ldsm4t(vl_, sb + VL + va);
                mma_bf16(o[2 * nb],     aph, vh_[0], vh_[1]);
                mma_bf16(o[2 * nb + 1], aph, vh_[2], vh_[3]);
                mma_bf16(o[2 * nb],     aph, vl_[0], vl_[1]);
                mma_bf16(o[2 * nb + 1], aph, vl_[2], vl_[3]);
                mma_bf16(o[2 * nb],     apl, vh_[0], vh_[1]);
                mma_bf16(o[2 * nb + 1], apl, vh_[2], vh_[3]);
            }
        }

        __syncthreads();            // all warps done reading V(j)
        load_V(j + 1);              // hides under next S
    }

    // ---- epilogue: O/l -> bf16 hi/lo ----
    const float inv0 = 1.0f / l0, inv1 = 1.0f / l1;
    const size_t obase = (size_t)b * AT_T * AT_C + (size_t)hd * AT_D;
    #pragma unroll
    for (int nf = 0; nf < 16; nf++) {
        int d = nf * 8 + 2 * (lane & 3);
        u32 h0, lo0, h1, lo1;
        pack2hl(o[nf][0] * inv0, o[nf][1] * inv0, h0, lo0);
        pack2hl(o[nf][2] * inv1, o[nf][3] * inv1, h1, lo1);
        size_t i0 = obase + (size_t)qrow0 * AT_C + d;
        size_t i1 = obase + (size_t)qrow1 * AT_C + d;
        *(u32*)(g_xoh + i0) = h0;  *(u32*)(g_xol + i0) = lo0;
        *(u32*)(g_xoh + i1) = h1;  *(u32*)(g_xol + i1) = lo1;
    }
}

// ---------------------------------------------------------------------------
// Launch: fused split -> merged QKV proj -> TC attention -> out proj
// ---------------------------------------------------------------------------
extern "C" void kernel_launch(void* const* d_in, const int* in_sizes, int n_in,
                              void* d_out, int out_size)
{
    const float* q   = (const float*)d_in[0];
    const float* k   = (const float*)d_in[1];
    const float* v   = (const float*)d_in[2];
    const float* ipw = (const float*)d_in[3];  // (3072, 2048)
    const float* ipb = (const float*)d_in[4];  // (3072,)
    const float* opw = (const float*)d_in[5];  // (2048, 2048)
    const float* opb = (const float*)d_in[6];  // (2048,)
    float* out = (float*)d_out;

    __nv_bfloat16 *qh, *ql, *kh, *kl, *vh, *vl, *wih, *wil, *woh, *wol;
    cudaGetSymbolAddress((void**)&qh, g_qh);   cudaGetSymbolAddress((void**)&ql, g_ql);
    cudaGetSymbolAddress((void**)&kh, g_kh);   cudaGetSymbolAddress((void**)&kl, g_kl);
    cudaGetSymbolAddress((void**)&vh, g_vh);   cudaGetSymbolAddress((void**)&vl, g_vl);
    cudaGetSymbolAddress((void**)&wih, g_wih); cudaGetSymbolAddress((void**)&wil, g_wil);
    cudaGetSymbolAddress((void**)&woh, g_woh); cudaGetSymbolAddress((void**)&wol, g_wol);

    const int attn_smem = 104448;  // (64+64+64) rows x 272 B x hi/lo
    cudaFuncSetAttribute(attn_tc_kernel, cudaFuncAttributeMaxDynamicSharedMemorySize, attn_smem);
    const int gemm_smem = 4 * STAGE_B;  // 98304
    cudaFuncSetAttribute(gemm_mma_proj, cudaFuncAttributeMaxDynamicSharedMemorySize, gemm_smem);
    cudaFuncSetAttribute(gemm_mma_out,  cudaFuncAttributeMaxDynamicSharedMemorySize, gemm_smem);

    dim3 blk(256);
    const int M_BLK = (AT_B * AT_T) / 128;  // 64

    // Fused prep: split inputs + weights into bf16 hi/lo (one launch)
    split_all_kernel<<<4096, 256>>>((const float4*)q, (const float4*)k, (const float4*)v,
                                    (const float4*)ipw, (const float4*)opw,
                                    (uint2*)qh, (uint2*)ql, (uint2*)kh, (uint2*)kl,
                                    (uint2*)vh, (uint2*)vl, (uint2*)wih, (uint2*)wil,
                                    (uint2*)woh, (uint2*)wol);

    // Merged Q+K+V projection (one launch, grid 24 x 64; Q pre-scaled)
    gemm_mma_proj<<<dim3(24, M_BLK), blk, gemm_smem>>>(ipb);

    // Tensor-core causal GQA flash attention (BM=64, occ 2, pipelined K/V)
    attn_tc_kernel<<<dim3(AT_B * AT_H, AT_T / 64), dim3(128), attn_smem>>>();

    // Output projection (fp32 out)
    gemm_mma_out<<<dim3(AT_C / 128, M_BLK), blk, gemm_smem>>>(opb, out);
}